// round 1
// baseline (speedup 1.0000x reference)
#include <cuda_runtime.h>
#include <cuda_bf16.h>

#define BDIM 8192
#define HDIM 1024
#define KDIM 1024

#define BM 128
#define BN 64
#define BK 16
#define XS_STRIDE (BM + 4)   // 132 floats, 528B rows (16B multiple)
#define WS_STRIDE (BN + 4)   // 68 floats, 272B rows (16B multiple)

// Scratch (allocation-free rule: __device__ globals)
__device__ float g_rh[(size_t)BDIM * HDIM];   // r * hidden
__device__ float g_z [(size_t)BDIM * HDIM];   // z gate
__device__ float g_c1[(size_t)BDIM * HDIM];   // input @ Wih^T + bih

__device__ __forceinline__ unsigned long long pack2(float lo, float hi) {
    unsigned long long v;
    asm("mov.b64 %0, {%1, %2};" : "=l"(v) : "f"(lo), "f"(hi));
    return v;
}
__device__ __forceinline__ void fma2(unsigned long long& d,
                                     unsigned long long a,
                                     unsigned long long b) {
    // packed fp32x2 FMA: {d.lo,d.hi} = {a.lo*b.lo+d.lo, a.hi*b.hi+d.hi}
    asm("fma.rn.f32x2 %0, %1, %2, %3;" : "=l"(d) : "l"(a), "l"(b), "l"(d));
}
__device__ __forceinline__ float lo2(unsigned long long v) {
    return __uint_as_float((unsigned)v);
}
__device__ __forceinline__ float hi2(unsigned long long v) {
    return __uint_as_float((unsigned)(v >> 32));
}
__device__ __forceinline__ float sigmoidf(float x) {
    return 1.0f / (1.0f + expf(-x));
}

// Fused GEMM: out[m,n] = epilogue( sum_k X1[m,k]*W1[n,k] (+ X2@W2 pass) )
// mode 0: rh   = sigmoid(acc + b1[n] + b2[n]) * hid        -> g_rh
// mode 1: z    = sigmoid(acc + b1[n] + b2[n])              -> g_z
// mode 2: c1   = acc + b1[n]                               -> g_c1
// mode 3: X := g_rh; ht = tanh(acc + b1[n] + g_c1);
//         newh = g_z*hid + (1-g_z)*ht                      -> out
__global__ __launch_bounds__(256, 3)
void gru_gemm(const float* __restrict__ X1, const float* __restrict__ W1,
              const float* __restrict__ b1,
              const float* __restrict__ X2, const float* __restrict__ W2,
              const float* __restrict__ b2,
              const float* __restrict__ hid,
              float* __restrict__ out, int mode)
{
    __shared__ __align__(16) float Xs[BK][XS_STRIDE];
    __shared__ __align__(16) float Ws[BK][WS_STRIDE];

    const int tid = threadIdx.x;
    const int tx = tid & 15;      // 0..15  (N direction, 4 cols each)
    const int ty = tid >> 4;      // 0..15  (M direction, 8 rows each)
    const int bm = blockIdx.y * BM;
    const int bn = blockIdx.x * BN;

    // loader coordinates
    const int xrow = tid >> 1;            // 0..127
    const int xcol = (tid & 1) * 8;       // 0 or 8
    const int wrow = tid >> 2;            // 0..63
    const int wcol = (tid & 3) * 4;       // 0,4,8,12

    unsigned long long acc[4][4];         // 4 m-pairs x 4 n cols, packed fp32x2
#pragma unroll
    for (int i = 0; i < 4; i++)
#pragma unroll
        for (int j = 0; j < 4; j++) acc[i][j] = 0ull;

    const int npass = (mode <= 1) ? 2 : 1;

    for (int pass = 0; pass < npass; ++pass) {
        const float* X = (mode == 3) ? (const float*)g_rh : (pass ? X2 : X1);
        const float* W = pass ? W2 : W1;
        const float* xg = X + (size_t)(bm + xrow) * KDIM + xcol;
        const float* wg = W + (size_t)(bn + wrow) * KDIM + wcol;

        for (int kt = 0; kt < KDIM; kt += BK) {
            float4 xa = *(const float4*)(xg + kt);
            float4 xb = *(const float4*)(xg + kt + 4);
            float4 wv = *(const float4*)(wg + kt);

            __syncthreads();   // previous tile fully consumed
            // transpose-store: Xs[k][m], Ws[k][n]
            Xs[xcol + 0][xrow] = xa.x;
            Xs[xcol + 1][xrow] = xa.y;
            Xs[xcol + 2][xrow] = xa.z;
            Xs[xcol + 3][xrow] = xa.w;
            Xs[xcol + 4][xrow] = xb.x;
            Xs[xcol + 5][xrow] = xb.y;
            Xs[xcol + 6][xrow] = xb.z;
            Xs[xcol + 7][xrow] = xb.w;
            Ws[wcol + 0][wrow] = wv.x;
            Ws[wcol + 1][wrow] = wv.y;
            Ws[wcol + 2][wrow] = wv.z;
            Ws[wcol + 3][wrow] = wv.w;
            __syncthreads();

#pragma unroll
            for (int k = 0; k < BK; ++k) {
                // 4 packed m-pairs (8 rows), contiguous in smem
                ulonglong2 ma = *(const ulonglong2*)(&Xs[k][ty * 8]);
                ulonglong2 mb = *(const ulonglong2*)(&Xs[k][ty * 8 + 4]);
                float4 nv = *(const float4*)(&Ws[k][tx * 4]);
                unsigned long long bx = pack2(nv.x, nv.x);
                unsigned long long by = pack2(nv.y, nv.y);
                unsigned long long bz = pack2(nv.z, nv.z);
                unsigned long long bw = pack2(nv.w, nv.w);

                fma2(acc[0][0], ma.x, bx); fma2(acc[0][1], ma.x, by);
                fma2(acc[0][2], ma.x, bz); fma2(acc[0][3], ma.x, bw);
                fma2(acc[1][0], ma.y, bx); fma2(acc[1][1], ma.y, by);
                fma2(acc[1][2], ma.y, bz); fma2(acc[1][3], ma.y, bw);
                fma2(acc[2][0], mb.x, bx); fma2(acc[2][1], mb.x, by);
                fma2(acc[2][2], mb.x, bz); fma2(acc[2][3], mb.x, bw);
                fma2(acc[3][0], mb.y, bx); fma2(acc[3][1], mb.y, by);
                fma2(acc[3][2], mb.y, bz); fma2(acc[3][3], mb.y, bw);
            }
        }
    }

    // ---- epilogue ----
    const int n0 = bn + tx * 4;
    float4 b1v = *(const float4*)&b1[n0];
    float4 b2v = make_float4(0.f, 0.f, 0.f, 0.f);
    if (mode <= 1) b2v = *(const float4*)&b2[n0];
    const float bsx = b1v.x + b2v.x;
    const float bsy = b1v.y + b2v.y;
    const float bsz = b1v.z + b2v.z;
    const float bsw = b1v.w + b2v.w;

    float* dst = (mode == 0) ? g_rh : (mode == 1) ? g_z
               : (mode == 2) ? g_c1 : out;

#pragma unroll
    for (int ip = 0; ip < 4; ip++) {
#pragma unroll
        for (int h = 0; h < 2; h++) {
            const int m = bm + ty * 8 + ip * 2 + h;
            const size_t idx = (size_t)m * HDIM + n0;
            float vx = h ? hi2(acc[ip][0]) : lo2(acc[ip][0]);
            float vy = h ? hi2(acc[ip][1]) : lo2(acc[ip][1]);
            float vz = h ? hi2(acc[ip][2]) : lo2(acc[ip][2]);
            float vw = h ? hi2(acc[ip][3]) : lo2(acc[ip][3]);
            float4 r;
            if (mode == 0) {
                float4 hv = *(const float4*)&hid[idx];
                r.x = sigmoidf(vx + bsx) * hv.x;
                r.y = sigmoidf(vy + bsy) * hv.y;
                r.z = sigmoidf(vz + bsz) * hv.z;
                r.w = sigmoidf(vw + bsw) * hv.w;
            } else if (mode == 1) {
                r.x = sigmoidf(vx + bsx);
                r.y = sigmoidf(vy + bsy);
                r.z = sigmoidf(vz + bsz);
                r.w = sigmoidf(vw + bsw);
            } else if (mode == 2) {
                r.x = vx + bsx; r.y = vy + bsy;
                r.z = vz + bsz; r.w = vw + bsw;
            } else {
                float4 c1v = *(const float4*)&g_c1[idx];
                float4 zv  = *(const float4*)&g_z[idx];
                float4 hv  = *(const float4*)&hid[idx];
                float htx = tanhf(vx + bsx + c1v.x);
                float hty = tanhf(vy + bsy + c1v.y);
                float htz = tanhf(vz + bsz + c1v.z);
                float htw = tanhf(vw + bsw + c1v.w);
                r.x = zv.x * hv.x + (1.0f - zv.x) * htx;
                r.y = zv.y * hv.y + (1.0f - zv.y) * hty;
                r.z = zv.z * hv.z + (1.0f - zv.z) * htz;
                r.w = zv.w * hv.w + (1.0f - zv.w) * htw;
            }
            *(float4*)&dst[idx] = r;
        }
    }
}

// One block per row: out = x - max - log(sum exp(x - max))
__global__ __launch_bounds__(256)
void logsoftmax_kernel(const float* __restrict__ nh, float* __restrict__ out)
{
    __shared__ float red[256];
    const int row = blockIdx.x;
    const int tid = threadIdx.x;
    const size_t base = (size_t)row * HDIM + tid * 4;
    const float4 v = *(const float4*)(nh + base);

    float m = fmaxf(fmaxf(v.x, v.y), fmaxf(v.z, v.w));
    red[tid] = m;
    __syncthreads();
#pragma unroll
    for (int s = 128; s >= 1; s >>= 1) {
        if (tid < s) red[tid] = fmaxf(red[tid], red[tid + s]);
        __syncthreads();
    }
    m = red[0];
    __syncthreads();

    float sum = expf(v.x - m) + expf(v.y - m) + expf(v.z - m) + expf(v.w - m);
    red[tid] = sum;
    __syncthreads();
#pragma unroll
    for (int s = 128; s >= 1; s >>= 1) {
        if (tid < s) red[tid] += red[tid + s];
        __syncthreads();
    }
    const float lse = m + logf(red[0]);

    float4 o = make_float4(v.x - lse, v.y - lse, v.z - lse, v.w - lse);
    *(float4*)(out + base) = o;
}

extern "C" void kernel_launch(void* const* d_in, const int* in_sizes, int n_in,
                              void* d_out, int out_size)
{
    const float* input  = (const float*)d_in[0];
    const float* hidden = (const float*)d_in[1];
    const float* Wir = (const float*)d_in[2];
    const float* bir = (const float*)d_in[3];
    const float* Whr = (const float*)d_in[4];
    const float* bhr = (const float*)d_in[5];
    const float* Wiz = (const float*)d_in[6];
    const float* biz = (const float*)d_in[7];
    const float* Whz = (const float*)d_in[8];
    const float* bhz = (const float*)d_in[9];
    const float* Wih = (const float*)d_in[10];
    const float* bih = (const float*)d_in[11];
    const float* Whh = (const float*)d_in[12];
    const float* bhh = (const float*)d_in[13];

    float* out  = (float*)d_out;                       // [B,H] log_softmax
    float* newh = out + (size_t)BDIM * HDIM;           // [B,H] new hidden

    dim3 grid(HDIM / BN, BDIM / BM);   // (16, 64)

    // r gate -> g_rh = sigmoid(.)*hidden
    gru_gemm<<<grid, 256>>>(input, Wir, bir, hidden, Whr, bhr, hidden, nullptr, 0);
    // z gate -> g_z
    gru_gemm<<<grid, 256>>>(input, Wiz, biz, hidden, Whz, bhz, nullptr, nullptr, 1);
    // c1 = input@Wih^T + bih -> g_c1
    gru_gemm<<<grid, 256>>>(input, Wih, bih, nullptr, nullptr, nullptr, nullptr, nullptr, 2);
    // c2 = g_rh@Whh^T; fuse tanh + update -> newh (d_out second half)
    gru_gemm<<<grid, 256>>>(nullptr, Whh, bhh, nullptr, nullptr, nullptr, hidden, newh, 3);
    // log_softmax(newh) -> out (d_out first half)
    logsoftmax_kernel<<<BDIM, 256>>>(newh, out);
}

// round 3
// speedup vs baseline: 1.5422x; 1.5422x over previous
#include <cuda_runtime.h>
#include <cuda_bf16.h>
#include <cstdint>

#define BDIM 8192
#define HDIM 1024

// ---------------- scratch (__device__ globals; no allocation) ----------------
__device__ __nv_bfloat16 g_XH[(size_t)BDIM * 2048];   // [input_hi | hidden_hi]
__device__ __nv_bfloat16 g_XL[(size_t)BDIM * 2048];   // [input_lo | hidden_lo]
__device__ __nv_bfloat16 g_RHh[(size_t)BDIM * 1024];  // hi(r*hidden)
__device__ __nv_bfloat16 g_RHl[(size_t)BDIM * 1024];  // lo(r*hidden)
__device__ __nv_bfloat16 g_WrH[2048 * 1024];          // [Wir|Whr] hi  (rows=H, cols=2048)
__device__ __nv_bfloat16 g_WrL[2048 * 1024];
__device__ __nv_bfloat16 g_WzH[2048 * 1024];
__device__ __nv_bfloat16 g_WzL[2048 * 1024];
__device__ __nv_bfloat16 g_WhH[2048 * 1024];          // [Wih|Whh]
__device__ __nv_bfloat16 g_WhL[2048 * 1024];
__device__ float g_zb[(size_t)BDIM * 1024];           // z gate fp32

// ---------------- helpers ----------------
__device__ __forceinline__ uint32_t smem_u32(const void* p) {
    uint32_t a;
    asm("{ .reg .u64 t; cvta.to.shared.u64 t, %1; cvt.u32.u64 %0, t; }"
        : "=r"(a) : "l"(p));
    return a;
}
#define CP16(sa, ga) \
    asm volatile("cp.async.cg.shared.global [%0], [%1], 16;" :: "r"(sa), "l"(ga) : "memory")
#define CP_COMMIT() asm volatile("cp.async.commit_group;" ::: "memory")
#define CP_WAIT2()  asm volatile("cp.async.wait_group 2;" ::: "memory")

__device__ __forceinline__ void ldm_x4(uint32_t* r, uint32_t addr) {
    asm volatile("ldmatrix.sync.aligned.m8n8.x4.shared.b16 {%0,%1,%2,%3}, [%4];"
                 : "=r"(r[0]), "=r"(r[1]), "=r"(r[2]), "=r"(r[3]) : "r"(addr));
}
__device__ __forceinline__ void mma16816(float* d, const uint32_t* a,
                                         uint32_t b0, uint32_t b1) {
    asm volatile(
        "mma.sync.aligned.m16n8k16.row.col.f32.bf16.bf16.f32 "
        "{%0,%1,%2,%3}, {%4,%5,%6,%7}, {%8,%9}, {%0,%1,%2,%3};"
        : "+f"(d[0]), "+f"(d[1]), "+f"(d[2]), "+f"(d[3])
        : "r"(a[0]), "r"(a[1]), "r"(a[2]), "r"(a[3]), "r"(b0), "r"(b1));
}
__device__ __forceinline__ float sigm(float x) { return 1.0f / (1.0f + __expf(-x)); }

// smem geometry: rows padded to 40 bf16 (80B, 16B-multiple) for conflict-free ldmatrix
#define ROWP 40
#define STAGE_ELEMS (2 * 128 * ROWP)        // A tile + B tile = 10240 elems
#define NSTAGE 4
#define SMEM_BYTES (NSTAGE * STAGE_ELEMS * 2)  // 81920 B

// ---------------- convert: fp32 -> bf16 hi/lo into selected buffer ----------------
__global__ void convert_split(const float* __restrict__ src, int dsel, int coff, int total4)
{
    int i = blockIdx.x * blockDim.x + threadIdx.x;
    if (i >= total4) return;
    __nv_bfloat16* dh = (dsel == 0) ? g_XH : (dsel == 1) ? g_WrH
                      : (dsel == 2) ? g_WzH : g_WhH;
    __nv_bfloat16* dl = (dsel == 0) ? g_XL : (dsel == 1) ? g_WrL
                      : (dsel == 2) ? g_WzL : g_WhL;
    int e = i * 4;
    int row = e >> 10;            // src has 1024 cols
    int col = e & 1023;
    float4 v = *(const float4*)(src + e);
    __nv_bfloat16 h0 = __float2bfloat16(v.x);
    __nv_bfloat16 h1 = __float2bfloat16(v.y);
    __nv_bfloat16 h2 = __float2bfloat16(v.z);
    __nv_bfloat16 h3 = __float2bfloat16(v.w);
    __nv_bfloat16 l0 = __float2bfloat16(v.x - __bfloat162float(h0));
    __nv_bfloat16 l1 = __float2bfloat16(v.y - __bfloat162float(h1));
    __nv_bfloat16 l2 = __float2bfloat16(v.z - __bfloat162float(h2));
    __nv_bfloat16 l3 = __float2bfloat16(v.w - __bfloat162float(h3));
    size_t d = (size_t)row * 2048 + coff + col;
    *(__nv_bfloat162*)(dh + d)     = __halves2bfloat162(h0, h1);
    *(__nv_bfloat162*)(dh + d + 2) = __halves2bfloat162(h2, h3);
    *(__nv_bfloat162*)(dl + d)     = __halves2bfloat162(l0, l1);
    *(__nv_bfloat162*)(dl + d + 2) = __halves2bfloat162(l2, l3);
}

// ---------------- HMMA GEMM with fused GRU epilogues ----------------
// D[m,n] = sum over 192 chunks (3-term bf16 split, K'=3*2048) of A[m,k]*W[n,k]
// mode 0 (r): r=sigmoid(acc+b1+b2); hi/lo(r*hidden) -> g_RHh/g_RHl
// mode 1 (z): z=sigmoid(acc+b1+b2) -> g_zb
// mode 2 (h): ht=tanh(acc+b1+b2); newh=z*h+(1-z)*ht -> outf
__global__ __launch_bounds__(256, 2)
void gemm_mma(int wsel, int mode,
              const float* __restrict__ b1, const float* __restrict__ b2,
              const float* __restrict__ hid, float* __restrict__ outf)
{
    extern __shared__ __nv_bfloat16 smem[];
    const uint32_t sbase = smem_u32(smem);

    const int tid  = threadIdx.x;
    const int wid  = tid >> 5;
    const int lane = tid & 31;
    const int wm   = wid & 1;      // 2 warp rows (64 rows each)
    const int wn   = wid >> 1;     // 4 warp cols (32 cols each)
    const int bm   = blockIdx.y * 128;
    const int bn   = blockIdx.x * 128;

    const __nv_bfloat16* Wh = (wsel == 0) ? g_WrH : (wsel == 1) ? g_WzH : g_WhH;
    const __nv_bfloat16* Wl = (wsel == 0) ? g_WrL : (wsel == 1) ? g_WzL : g_WhL;

    // per-thread loader coords: 2x16B for A + 2x16B for B per chunk
    const int arow = tid >> 1;
    const int apart = (tid & 1) * 16;

    float acc[4][4][4];
#pragma unroll
    for (int i = 0; i < 4; i++)
#pragma unroll
        for (int j = 0; j < 4; j++) {
            acc[i][j][0] = 0.f; acc[i][j][1] = 0.f;
            acc[i][j][2] = 0.f; acc[i][j][3] = 0.f;
        }

    const int C = 192;   // 3 terms * 64 chunks

    // chunk loader
    auto load_chunk = [&](int c, int s) {
        const int t  = c >> 6;              // term 0,1,2
        const int kk = (c & 63) << 5;       // 0..2016
        const __nv_bfloat16* Bsrc = (t == 2) ? Wl : Wh;
        const __nv_bfloat16* Asrc;
        int lda, col;
        if (mode == 2 && kk >= 1024) {      // r*h region of concat A
            Asrc = (t == 1) ? g_RHl : g_RHh; lda = 1024; col = kk - 1024;
        } else {
            Asrc = (t == 1) ? g_XL : g_XH;   lda = 2048; col = kk;
        }
        const __nv_bfloat16* ag = Asrc + (size_t)(bm + arow) * lda + col + apart;
        const __nv_bfloat16* bg = Bsrc + (size_t)(bn + arow) * 2048 + kk + apart;
        uint32_t sa = sbase + (uint32_t)(s * STAGE_ELEMS + arow * ROWP + apart) * 2;
        uint32_t sb = sa + 128 * ROWP * 2;
        CP16(sa, ag);       CP16(sa + 16, ag + 8);
        CP16(sb, bg);       CP16(sb + 16, bg + 8);
    };

    // prologue: stages 0..2
#pragma unroll
    for (int s = 0; s < NSTAGE - 1; ++s) { load_chunk(s, s); CP_COMMIT(); }

    const int a_lrow = lane & 15;
    const int a_lcol = (lane >> 4) << 3;
    const int b_lrow = lane >> 2;
    const int b_lcol = (lane & 3) * 2;

    for (int c = 0; c < C; ++c) {
        CP_WAIT2();
        __syncthreads();
        const int nc = c + NSTAGE - 1;
        if (nc < C) load_chunk(nc, nc & (NSTAGE - 1));
        CP_COMMIT();

        const int s = c & (NSTAGE - 1);
        const uint32_t aB = sbase + (uint32_t)(s * STAGE_ELEMS) * 2;
        const __nv_bfloat16* bT = smem + s * STAGE_ELEMS + 128 * ROWP;

#pragma unroll
        for (int ks = 0; ks < 2; ++ks) {
            const int kb = ks * 16;
            uint32_t af[4][4];
#pragma unroll
            for (int mi = 0; mi < 4; ++mi) {
                uint32_t ad = aB + (uint32_t)((wm * 64 + mi * 16 + a_lrow) * ROWP
                                              + kb + a_lcol) * 2;
                ldm_x4(af[mi], ad);
            }
            uint32_t bf0[4], bf1[4];
#pragma unroll
            for (int ni = 0; ni < 4; ++ni) {
                const __nv_bfloat16* bp = bT + (wn * 32 + ni * 8 + b_lrow) * ROWP
                                             + kb + b_lcol;
                bf0[ni] = *(const uint32_t*)bp;
                bf1[ni] = *(const uint32_t*)(bp + 8);
            }
#pragma unroll
            for (int mi = 0; mi < 4; ++mi)
#pragma unroll
                for (int ni = 0; ni < 4; ++ni)
                    mma16816(acc[mi][ni], af[mi], bf0[ni], bf1[ni]);
        }
    }

    // ---------------- epilogue ----------------
    const int r_lane = lane >> 2;
    const int c_lane = (lane & 3) * 2;

#pragma unroll
    for (int mi = 0; mi < 4; ++mi) {
        const int r0 = bm + wm * 64 + mi * 16 + r_lane;
#pragma unroll
        for (int ni = 0; ni < 4; ++ni) {
            const int n = bn + wn * 32 + ni * 8 + c_lane;
            const float bs0 = b1[n] + b2[n];
            const float bs1 = b1[n + 1] + b2[n + 1];
#pragma unroll
            for (int h = 0; h < 2; ++h) {
                const int row = r0 + h * 8;
                const size_t idx = (size_t)row * HDIM + n;
                float v0 = acc[mi][ni][h * 2 + 0] + bs0;
                float v1 = acc[mi][ni][h * 2 + 1] + bs1;
                if (mode == 0) {
                    float2 hv = *(const float2*)(hid + idx);
                    float rv0 = hv.x * sigm(v0);
                    float rv1 = hv.y * sigm(v1);
                    __nv_bfloat16 h0 = __float2bfloat16(rv0);
                    __nv_bfloat16 h1 = __float2bfloat16(rv1);
                    *(__nv_bfloat162*)(g_RHh + idx) = __halves2bfloat162(h0, h1);
                    __nv_bfloat16 l0 = __float2bfloat16(rv0 - __bfloat162float(h0));
                    __nv_bfloat16 l1 = __float2bfloat16(rv1 - __bfloat162float(h1));
                    *(__nv_bfloat162*)(g_RHl + idx) = __halves2bfloat162(l0, l1);
                } else if (mode == 1) {
                    float2 z = make_float2(sigm(v0), sigm(v1));
                    *(float2*)(g_zb + idx) = z;
                } else {
                    float2 zv = *(const float2*)(g_zb + idx);
                    float2 hv = *(const float2*)(hid + idx);
                    float t0 = tanhf(v0), t1 = tanhf(v1);
                    float2 o;
                    o.x = zv.x * hv.x + (1.0f - zv.x) * t0;
                    o.y = zv.y * hv.y + (1.0f - zv.y) * t1;
                    *(float2*)(outf + idx) = o;
                }
            }
        }
    }
}

// ---------------- log-softmax over rows of new_hidden ----------------
__global__ __launch_bounds__(256)
void logsoftmax_kernel(const float* __restrict__ nh, float* __restrict__ out)
{
    __shared__ float red[256];
    const int row = blockIdx.x;
    const int tid = threadIdx.x;
    const size_t base = (size_t)row * HDIM + tid * 4;
    const float4 v = *(const float4*)(nh + base);

    float m = fmaxf(fmaxf(v.x, v.y), fmaxf(v.z, v.w));
    red[tid] = m;
    __syncthreads();
#pragma unroll
    for (int s = 128; s >= 1; s >>= 1) {
        if (tid < s) red[tid] = fmaxf(red[tid], red[tid + s]);
        __syncthreads();
    }
    m = red[0];
    __syncthreads();

    float sum = expf(v.x - m) + expf(v.y - m) + expf(v.z - m) + expf(v.w - m);
    red[tid] = sum;
    __syncthreads();
#pragma unroll
    for (int s = 128; s >= 1; s >>= 1) {
        if (tid < s) red[tid] += red[tid + s];
        __syncthreads();
    }
    const float lse = m + logf(red[0]);
    float4 o = make_float4(v.x - lse, v.y - lse, v.z - lse, v.w - lse);
    *(float4*)(out + base) = o;
}

// ---------------- launch ----------------
extern "C" void kernel_launch(void* const* d_in, const int* in_sizes, int n_in,
                              void* d_out, int out_size)
{
    const float* input  = (const float*)d_in[0];
    const float* hidden = (const float*)d_in[1];
    const float* Wir = (const float*)d_in[2];
    const float* bir = (const float*)d_in[3];
    const float* Whr = (const float*)d_in[4];
    const float* bhr = (const float*)d_in[5];
    const float* Wiz = (const float*)d_in[6];
    const float* biz = (const float*)d_in[7];
    const float* Whz = (const float*)d_in[8];
    const float* bhz = (const float*)d_in[9];
    const float* Wih = (const float*)d_in[10];
    const float* bih = (const float*)d_in[11];
    const float* Whh = (const float*)d_in[12];
    const float* bhh = (const float*)d_in[13];

    float* out  = (float*)d_out;
    float* newh = out + (size_t)BDIM * HDIM;

    cudaFuncSetAttribute(gemm_mma, cudaFuncAttributeMaxDynamicSharedMemorySize, SMEM_BYTES);

    // converts: activations (8192 rows), weights (1024 rows each)
    const int T_ACT = BDIM * 1024 / 4, T_W = 1024 * 1024 / 4;
    convert_split<<<(T_ACT + 255) / 256, 256>>>(input,  0, 0,    T_ACT);
    convert_split<<<(T_ACT + 255) / 256, 256>>>(hidden, 0, 1024, T_ACT);
    convert_split<<<(T_W + 255) / 256, 256>>>(Wir, 1, 0,    T_W);
    convert_split<<<(T_W + 255) / 256, 256>>>(Whr, 1, 1024, T_W);
    convert_split<<<(T_W + 255) / 256, 256>>>(Wiz, 2, 0,    T_W);
    convert_split<<<(T_W + 255) / 256, 256>>>(Whz, 2, 1024, T_W);
    convert_split<<<(T_W + 255) / 256, 256>>>(Wih, 3, 0,    T_W);
    convert_split<<<(T_W + 255) / 256, 256>>>(Whh, 3, 1024, T_W);

    dim3 grid(HDIM / 128, BDIM / 128);   // (8, 64)
    // r gate -> RH hi/lo
    gemm_mma<<<grid, 256, SMEM_BYTES>>>(0, 0, bir, bhr, hidden, nullptr);
    // z gate -> g_zb
    gemm_mma<<<grid, 256, SMEM_BYTES>>>(1, 1, biz, bhz, hidden, nullptr);
    // candidate + update -> newh
    gemm_mma<<<grid, 256, SMEM_BYTES>>>(2, 2, bih, bhh, hidden, newh);

    logsoftmax_kernel<<<BDIM, 256>>>(newh, out);
}

// round 4
// speedup vs baseline: 2.8712x; 1.8618x over previous
#include <cuda_runtime.h>
#include <cuda_fp16.h>
#include <cstdint>

#define BDIM 8192
#define HDIM 1024

// ---------------- scratch (__device__ globals; no allocation) ----------------
__device__ __half g_XH[(size_t)BDIM * 2048];   // [input_hi | hidden_hi] fp16
__device__ __half g_XL[(size_t)BDIM * 2048];   // [input_lo | hidden_lo] fp16
__device__ __half g_RHh[(size_t)BDIM * 1024];  // hi(r*hidden)
__device__ __half g_RHl[(size_t)BDIM * 1024];  // lo(r*hidden)
__device__ __half g_Wrz[(size_t)2048 * 2048];  // rows: [Wr|Wz] gates, cols: [Wi|Wh]
__device__ __half g_Wch[(size_t)1024 * 2048];  // rows: Wh gate,     cols: [Wih|Whh]
__device__ float  g_zb[(size_t)BDIM * 1024];   // z gate fp32

// ---------------- helpers ----------------
__device__ __forceinline__ uint32_t smem_u32(const void* p) {
    uint32_t a;
    asm("{ .reg .u64 t; cvta.to.shared.u64 t, %1; cvt.u32.u64 %0, t; }"
        : "=r"(a) : "l"(p));
    return a;
}
#define CP16(sa, ga) \
    asm volatile("cp.async.cg.shared.global [%0], [%1], 16;" :: "r"(sa), "l"(ga) : "memory")
#define CP_COMMIT() asm volatile("cp.async.commit_group;" ::: "memory")
#define CP_WAIT1()  asm volatile("cp.async.wait_group 1;" ::: "memory")

__device__ __forceinline__ void ldm_x4(uint32_t* r, uint32_t addr) {
    asm volatile("ldmatrix.sync.aligned.m8n8.x4.shared.b16 {%0,%1,%2,%3}, [%4];"
                 : "=r"(r[0]), "=r"(r[1]), "=r"(r[2]), "=r"(r[3]) : "r"(addr));
}
__device__ __forceinline__ void mma16816(float* d, const uint32_t* a,
                                         uint32_t b0, uint32_t b1) {
    asm volatile(
        "mma.sync.aligned.m16n8k16.row.col.f32.f16.f16.f32 "
        "{%0,%1,%2,%3}, {%4,%5,%6,%7}, {%8,%9}, {%0,%1,%2,%3};"
        : "+f"(d[0]), "+f"(d[1]), "+f"(d[2]), "+f"(d[3])
        : "r"(a[0]), "r"(a[1]), "r"(a[2]), "r"(a[3]), "r"(b0), "r"(b1));
}
__device__ __forceinline__ float sigm(float x) { return 1.0f / (1.0f + __expf(-x)); }

// smem geometry: rows padded to 40 fp16 (80B) -> conflict-free ldmatrix/LDS
#define ROWP 40
#define TILE_BYTES (128 * ROWP * 2)          // 10240 B per 128x32 tile
#define STAGE_ELEMS (3 * 128 * ROWP)         // Ah + Al + B = 15360 halves
#define NSTAGE 3
#define SMEM_BYTES (NSTAGE * STAGE_ELEMS * 2)  // 92160 B

// ---------------- converts ----------------
// activations: fp32 -> fp16 hi/lo into [input|hidden] concat
__global__ void convert_act(const float* __restrict__ a, const float* __restrict__ b,
                            int total4)
{
    int i = blockIdx.x * blockDim.x + threadIdx.x;
    if (i >= total4) return;
    const float* src = blockIdx.y ? b : a;
    const int coff = blockIdx.y ? 1024 : 0;
    int e = i * 4;
    int row = e >> 10;
    int col = e & 1023;
    float4 v = *(const float4*)(src + e);
    __half h0 = __float2half(v.x), h1 = __float2half(v.y);
    __half h2 = __float2half(v.z), h3 = __float2half(v.w);
    __half l0 = __float2half(v.x - __half2float(h0));
    __half l1 = __float2half(v.y - __half2float(h1));
    __half l2 = __float2half(v.z - __half2float(h2));
    __half l3 = __float2half(v.w - __half2float(h3));
    size_t d = (size_t)row * 2048 + coff + col;
    *(__half2*)(g_XH + d)     = __halves2half2(h0, h1);
    *(__half2*)(g_XH + d + 2) = __halves2half2(h2, h3);
    *(__half2*)(g_XL + d)     = __halves2half2(l0, l1);
    *(__half2*)(g_XL + d + 2) = __halves2half2(l2, l3);
}

// weights: fp32 -> single fp16, 6 slices via blockIdx.z
__global__ void convert_w(const float* __restrict__ Wir, const float* __restrict__ Whr,
                          const float* __restrict__ Wiz, const float* __restrict__ Whz,
                          const float* __restrict__ Wih, const float* __restrict__ Whh,
                          int total4)
{
    int i = blockIdx.x * blockDim.x + threadIdx.x;
    if (i >= total4) return;
    const int z = blockIdx.z;
    const float* src = (z == 0) ? Wir : (z == 1) ? Whr : (z == 2) ? Wiz
                     : (z == 3) ? Whz : (z == 4) ? Wih : Whh;
    __half* dst = (z < 4) ? g_Wrz : g_Wch;
    const int roff = (z == 2 || z == 3) ? 1024 : 0;
    const int coff = (z & 1) ? 1024 : 0;
    int e = i * 4;
    int row = e >> 10;
    int col = e & 1023;
    float4 v = *(const float4*)(src + e);
    size_t d = (size_t)(roff + row) * 2048 + coff + col;
    *(__half2*)(dst + d)     = __halves2half2(__float2half(v.x), __float2half(v.y));
    *(__half2*)(dst + d + 2) = __halves2half2(__float2half(v.z), __float2half(v.w));
}

// ---------------- HMMA GEMM, fp16 2-term (A hi/lo, B single) ----------------
// mode 0: N=2048 rz-GEMM over A=[in|hid]; bn<1024 -> r epilogue (RH hi/lo),
//         else z epilogue (g_zb)
// mode 1: N=1024 candidate GEMM over A=[in|r*h]; newh epilogue -> outf
__global__ __launch_bounds__(256, 2)
void gemm_mma(int mode,
              const float* __restrict__ bi0, const float* __restrict__ bh0,
              const float* __restrict__ bi1, const float* __restrict__ bh1,
              const float* __restrict__ hid, float* __restrict__ outf)
{
    extern __shared__ __half smem[];
    const uint32_t sbase = smem_u32(smem);

    const int tid  = threadIdx.x;
    const int wid  = tid >> 5;
    const int lane = tid & 31;
    const int wm   = wid & 1;      // 2 warp rows (64 rows each)
    const int wn   = wid >> 1;     // 4 warp cols (32 cols each)
    const int bm   = blockIdx.y * 128;
    const int bn   = blockIdx.x * 128;

    const __half* Bw = (mode == 0) ? g_Wrz : g_Wch;

    const int row  = tid >> 1;          // loader row 0..127
    const int part = (tid & 1) * 16;    // loader col part (elems)

    float acc[4][4][4];
#pragma unroll
    for (int i = 0; i < 4; i++)
#pragma unroll
        for (int j = 0; j < 4; j++) {
            acc[i][j][0] = 0.f; acc[i][j][1] = 0.f;
            acc[i][j][2] = 0.f; acc[i][j][3] = 0.f;
        }

    const int C = 64;   // K=2048, chunk=32

    auto load_chunk = [&](int c, int s) {
        const int kk = c << 5;
        const __half *Ah, *Al;
        int lda, col;
        if (mode == 1 && kk >= 1024) { Ah = g_RHh; Al = g_RHl; lda = 1024; col = kk - 1024; }
        else                         { Ah = g_XH;  Al = g_XL;  lda = 2048; col = kk; }
        const __half* ah = Ah + (size_t)(bm + row) * lda + col + part;
        const __half* al = Al + (size_t)(bm + row) * lda + col + part;
        const __half* bg = Bw + (size_t)(bn + row) * 2048 + kk + part;
        uint32_t sa = sbase + (uint32_t)(s * STAGE_ELEMS + row * ROWP + part) * 2;
        CP16(sa, ah);                   CP16(sa + 16, ah + 8);
        CP16(sa + TILE_BYTES, al);      CP16(sa + TILE_BYTES + 16, al + 8);
        CP16(sa + 2 * TILE_BYTES, bg);  CP16(sa + 2 * TILE_BYTES + 16, bg + 8);
    };

    load_chunk(0, 0); CP_COMMIT();
    load_chunk(1, 1); CP_COMMIT();

    const int a_lrow = lane & 15;
    const int a_lcol = (lane >> 4) << 3;
    const int b_lrow = lane >> 2;
    const int b_lcol = (lane & 3) * 2;

    int sc = 0;
    for (int c = 0; c < C; ++c) {
        CP_WAIT1();
        __syncthreads();
        if (c + 2 < C) {
            int s2 = sc + 2; if (s2 >= 3) s2 -= 3;
            load_chunk(c + 2, s2);
        }
        CP_COMMIT();

        const uint32_t aHb = sbase + (uint32_t)(sc * STAGE_ELEMS) * 2;
        const uint32_t aLb = aHb + TILE_BYTES;
        const __half* bT = smem + sc * STAGE_ELEMS + 2 * 128 * ROWP;

#pragma unroll
        for (int ks = 0; ks < 2; ++ks) {
            const int kb = ks * 16;
            uint32_t bf0[4], bf1[4];
#pragma unroll
            for (int ni = 0; ni < 4; ++ni) {
                const __half* bp = bT + (wn * 32 + ni * 8 + b_lrow) * ROWP + kb + b_lcol;
                bf0[ni] = *(const uint32_t*)bp;
                bf1[ni] = *(const uint32_t*)(bp + 8);
            }
            uint32_t ah[4][4], al[4][4];
#pragma unroll
            for (int mi = 0; mi < 4; ++mi) {
                uint32_t off = (uint32_t)((wm * 64 + mi * 16 + a_lrow) * ROWP
                                          + kb + a_lcol) * 2;
                ldm_x4(ah[mi], aHb + off);
                ldm_x4(al[mi], aLb + off);
            }
#pragma unroll
            for (int mi = 0; mi < 4; ++mi)
#pragma unroll
                for (int ni = 0; ni < 4; ++ni) {
                    mma16816(acc[mi][ni], ah[mi], bf0[ni], bf1[ni]);
                    mma16816(acc[mi][ni], al[mi], bf0[ni], bf1[ni]);
                }
        }
        ++sc; if (sc == 3) sc = 0;
    }

    // ---------------- epilogue ----------------
    const int r_lane = lane >> 2;
    const int c_lane = (lane & 3) * 2;
    const bool is_r = (mode == 0) && (bn < 1024);

#pragma unroll
    for (int mi = 0; mi < 4; ++mi) {
        const int r0 = bm + wm * 64 + mi * 16 + r_lane;
#pragma unroll
        for (int ni = 0; ni < 4; ++ni) {
            const int n_ = bn + wn * 32 + ni * 8 + c_lane;
            const int gn = (mode == 0 && n_ >= 1024) ? n_ - 1024 : n_;
            float bs0, bs1;
            if (mode == 1 || is_r) { bs0 = bi0[gn] + bh0[gn]; bs1 = bi0[gn + 1] + bh0[gn + 1]; }
            else                   { bs0 = bi1[gn] + bh1[gn]; bs1 = bi1[gn + 1] + bh1[gn + 1]; }
#pragma unroll
            for (int h = 0; h < 2; ++h) {
                const int rr = r0 + h * 8;
                const size_t idx = (size_t)rr * HDIM + gn;
                float v0 = acc[mi][ni][h * 2 + 0] + bs0;
                float v1 = acc[mi][ni][h * 2 + 1] + bs1;
                if (mode == 0) {
                    if (is_r) {
                        float2 hv = *(const float2*)(hid + idx);
                        float rv0 = hv.x * sigm(v0);
                        float rv1 = hv.y * sigm(v1);
                        __half h0 = __float2half(rv0);
                        __half h1 = __float2half(rv1);
                        *(__half2*)(g_RHh + idx) = __halves2half2(h0, h1);
                        __half l0 = __float2half(rv0 - __half2float(h0));
                        __half l1 = __float2half(rv1 - __half2float(h1));
                        *(__half2*)(g_RHl + idx) = __halves2half2(l0, l1);
                    } else {
                        *(float2*)(g_zb + idx) = make_float2(sigm(v0), sigm(v1));
                    }
                } else {
                    float2 zv = *(const float2*)(g_zb + idx);
                    float2 hv = *(const float2*)(hid + idx);
                    float t0 = tanhf(v0), t1 = tanhf(v1);
                    float2 o;
                    o.x = zv.x * hv.x + (1.0f - zv.x) * t0;
                    o.y = zv.y * hv.y + (1.0f - zv.y) * t1;
                    *(float2*)(outf + idx) = o;
                }
            }
        }
    }
}

// ---------------- log-softmax over rows of new_hidden ----------------
__global__ __launch_bounds__(256)
void logsoftmax_kernel(const float* __restrict__ nh, float* __restrict__ out)
{
    __shared__ float red[256];
    const int row = blockIdx.x;
    const int tid = threadIdx.x;
    const size_t base = (size_t)row * HDIM + tid * 4;
    const float4 v = *(const float4*)(nh + base);

    float m = fmaxf(fmaxf(v.x, v.y), fmaxf(v.z, v.w));
    red[tid] = m;
    __syncthreads();
#pragma unroll
    for (int s = 128; s >= 1; s >>= 1) {
        if (tid < s) red[tid] = fmaxf(red[tid], red[tid + s]);
        __syncthreads();
    }
    m = red[0];
    __syncthreads();

    float sum = expf(v.x - m) + expf(v.y - m) + expf(v.z - m) + expf(v.w - m);
    red[tid] = sum;
    __syncthreads();
#pragma unroll
    for (int s = 128; s >= 1; s >>= 1) {
        if (tid < s) red[tid] += red[tid + s];
        __syncthreads();
    }
    const float lse = m + logf(red[0]);
    float4 o = make_float4(v.x - lse, v.y - lse, v.z - lse, v.w - lse);
    *(float4*)(out + base) = o;
}

// ---------------- launch ----------------
extern "C" void kernel_launch(void* const* d_in, const int* in_sizes, int n_in,
                              void* d_out, int out_size)
{
    const float* input  = (const float*)d_in[0];
    const float* hidden = (const float*)d_in[1];
    const float* Wir = (const float*)d_in[2];
    const float* bir = (const float*)d_in[3];
    const float* Whr = (const float*)d_in[4];
    const float* bhr = (const float*)d_in[5];
    const float* Wiz = (const float*)d_in[6];
    const float* biz = (const float*)d_in[7];
    const float* Whz = (const float*)d_in[8];
    const float* bhz = (const float*)d_in[9];
    const float* Wih = (const float*)d_in[10];
    const float* bih = (const float*)d_in[11];
    const float* Whh = (const float*)d_in[12];
    const float* bhh = (const float*)d_in[13];

    float* out  = (float*)d_out;
    float* newh = out + (size_t)BDIM * HDIM;

    cudaFuncSetAttribute(gemm_mma, cudaFuncAttributeMaxDynamicSharedMemorySize, SMEM_BYTES);

    const int T_ACT = BDIM * 1024 / 4;       // 2M float4 per source
    const int T_W = 1024 * 1024 / 4;
    {
        dim3 ga((T_ACT + 255) / 256, 2);
        convert_act<<<ga, 256>>>(input, hidden, T_ACT);
        dim3 gw((T_W + 255) / 256, 1, 6);
        convert_w<<<gw, 256>>>(Wir, Whr, Wiz, Whz, Wih, Whh, T_W);
    }

    // fused r+z GEMM: N=2048
    dim3 grid1(2048 / 128, BDIM / 128);      // (16, 64)
    gemm_mma<<<grid1, 256, SMEM_BYTES>>>(0, bir, bhr, biz, bhz, hidden, nullptr);
    // candidate GEMM: N=1024, A=[input | r*h]
    dim3 grid2(HDIM / 128, BDIM / 128);      // (8, 64)
    gemm_mma<<<grid2, 256, SMEM_BYTES>>>(1, bih, bhh, nullptr, nullptr, hidden, newh);

    logsoftmax_kernel<<<BDIM, 256>>>(newh, out);
}

// round 5
// speedup vs baseline: 2.9916x; 1.0419x over previous
#include <cuda_runtime.h>
#include <cuda_fp16.h>
#include <cstdint>

#define BDIM 8192
#define HDIM 1024

// ---------------- scratch (__device__ globals; no allocation) ----------------
__device__ __half g_XH[(size_t)BDIM * 2048];   // [input_hi | hidden_hi] fp16
__device__ __half g_XL[(size_t)BDIM * 2048];   // [input_lo | hidden_lo] fp16
__device__ __half g_RHh[(size_t)BDIM * 1024];  // hi(r*hidden)
__device__ __half g_RHl[(size_t)BDIM * 1024];  // lo(r*hidden)
__device__ __half g_Wrz[(size_t)2048 * 2048];  // rows: [Wr|Wz] gates, cols: [Wi|Wh]
__device__ __half g_Wch[(size_t)1024 * 2048];  // rows: Wh gate,     cols: [Wih|Whh]
__device__ float  g_zb[(size_t)BDIM * 1024];   // z gate fp32

// ---------------- helpers ----------------
__device__ __forceinline__ uint32_t smem_u32(const void* p) {
    uint32_t a;
    asm("{ .reg .u64 t; cvta.to.shared.u64 t, %1; cvt.u32.u64 %0, t; }"
        : "=r"(a) : "l"(p));
    return a;
}
#define CP16(sa, ga) \
    asm volatile("cp.async.cg.shared.global [%0], [%1], 16;" :: "r"(sa), "l"(ga) : "memory")
#define CP_COMMIT() asm volatile("cp.async.commit_group;" ::: "memory")
#define CP_WAIT1()  asm volatile("cp.async.wait_group 1;" ::: "memory")

__device__ __forceinline__ void ldm_x4(uint32_t* r, uint32_t addr) {
    asm volatile("ldmatrix.sync.aligned.m8n8.x4.shared.b16 {%0,%1,%2,%3}, [%4];"
                 : "=r"(r[0]), "=r"(r[1]), "=r"(r[2]), "=r"(r[3]) : "r"(addr));
}
__device__ __forceinline__ void mma16816(float* d, const uint32_t* a,
                                         uint32_t b0, uint32_t b1) {
    asm volatile(
        "mma.sync.aligned.m16n8k16.row.col.f32.f16.f16.f32 "
        "{%0,%1,%2,%3}, {%4,%5,%6,%7}, {%8,%9}, {%0,%1,%2,%3};"
        : "+f"(d[0]), "+f"(d[1]), "+f"(d[2]), "+f"(d[3])
        : "r"(a[0]), "r"(a[1]), "r"(a[2]), "r"(a[3]), "r"(b0), "r"(b1));
}
__device__ __forceinline__ float sigm(float x) { return 1.0f / (1.0f + __expf(-x)); }

// smem geometry: rows padded to 40 fp16 (80B) -> conflict-free ldmatrix
#define ROWP 40
#define TILE_BYTES (128 * ROWP * 2)          // 10240 B per 128x32 tile
#define STAGE_ELEMS (3 * 128 * ROWP)         // Ah + Al + B = 15360 halves
#define NSTAGE 3
#define SMEM_BYTES (NSTAGE * STAGE_ELEMS * 2)  // 92160 B

// ---------------- converts ----------------
__global__ void convert_act(const float* __restrict__ a, const float* __restrict__ b,
                            int total4)
{
    int i = blockIdx.x * blockDim.x + threadIdx.x;
    if (i >= total4) return;
    const float* src = blockIdx.y ? b : a;
    const int coff = blockIdx.y ? 1024 : 0;
    int e = i * 4;
    int row = e >> 10;
    int col = e & 1023;
    float4 v = *(const float4*)(src + e);
    __half h0 = __float2half(v.x), h1 = __float2half(v.y);
    __half h2 = __float2half(v.z), h3 = __float2half(v.w);
    __half l0 = __float2half(v.x - __half2float(h0));
    __half l1 = __float2half(v.y - __half2float(h1));
    __half l2 = __float2half(v.z - __half2float(h2));
    __half l3 = __float2half(v.w - __half2float(h3));
    size_t d = (size_t)row * 2048 + coff + col;
    *(__half2*)(g_XH + d)     = __halves2half2(h0, h1);
    *(__half2*)(g_XH + d + 2) = __halves2half2(h2, h3);
    *(__half2*)(g_XL + d)     = __halves2half2(l0, l1);
    *(__half2*)(g_XL + d + 2) = __halves2half2(l2, l3);
}

__global__ void convert_w(const float* __restrict__ Wir, const float* __restrict__ Whr,
                          const float* __restrict__ Wiz, const float* __restrict__ Whz,
                          const float* __restrict__ Wih, const float* __restrict__ Whh,
                          int total4)
{
    int i = blockIdx.x * blockDim.x + threadIdx.x;
    if (i >= total4) return;
    const int z = blockIdx.z;
    const float* src = (z == 0) ? Wir : (z == 1) ? Whr : (z == 2) ? Wiz
                     : (z == 3) ? Whz : (z == 4) ? Wih : Whh;
    __half* dst = (z < 4) ? g_Wrz : g_Wch;
    const int roff = (z == 2 || z == 3) ? 1024 : 0;
    const int coff = (z & 1) ? 1024 : 0;
    int e = i * 4;
    int row = e >> 10;
    int col = e & 1023;
    float4 v = *(const float4*)(src + e);
    size_t d = (size_t)(roff + row) * 2048 + coff + col;
    *(__half2*)(dst + d)     = __halves2half2(__float2half(v.x), __float2half(v.y));
    *(__half2*)(dst + d + 2) = __halves2half2(__float2half(v.z), __float2half(v.w));
}

// ---------------- HMMA GEMM, fp16 2-term (A hi/lo, B single) ----------------
// warp grid 4x2: warp tile 32 rows x 64 cols
// mode 0: N=2048 rz-GEMM over A=[in|hid]; bn<1024 -> r epilogue, else z
// mode 1: N=1024 candidate GEMM over A=[in|r*h]; newh epilogue -> outf
__global__ __launch_bounds__(256, 2)
void gemm_mma(int mode,
              const float* __restrict__ bi0, const float* __restrict__ bh0,
              const float* __restrict__ bi1, const float* __restrict__ bh1,
              const float* __restrict__ hid, float* __restrict__ outf)
{
    extern __shared__ __half smem[];
    const uint32_t sbase = smem_u32(smem);

    const int tid  = threadIdx.x;
    const int wid  = tid >> 5;
    const int lane = tid & 31;
    const int wm   = wid & 3;      // 4 warp rows (32 rows each)
    const int wn   = wid >> 2;     // 2 warp cols (64 cols each)
    const int bm   = blockIdx.y * 128;
    const int bn   = blockIdx.x * 128;

    const __half* Bw = (mode == 0) ? g_Wrz : g_Wch;

    const int row  = tid >> 1;          // loader row 0..127
    const int part = (tid & 1) * 16;    // loader col part (elems)

    float acc[2][8][4];
#pragma unroll
    for (int i = 0; i < 2; i++)
#pragma unroll
        for (int j = 0; j < 8; j++) {
            acc[i][j][0] = 0.f; acc[i][j][1] = 0.f;
            acc[i][j][2] = 0.f; acc[i][j][3] = 0.f;
        }

    const int C = 64;   // K=2048, chunk=32

    auto load_chunk = [&](int c, int s) {
        const int kk = c << 5;
        const __half *Ah, *Al;
        int lda, col;
        if (mode == 1 && kk >= 1024) { Ah = g_RHh; Al = g_RHl; lda = 1024; col = kk - 1024; }
        else                         { Ah = g_XH;  Al = g_XL;  lda = 2048; col = kk; }
        const __half* ah = Ah + (size_t)(bm + row) * lda + col + part;
        const __half* al = Al + (size_t)(bm + row) * lda + col + part;
        const __half* bg = Bw + (size_t)(bn + row) * 2048 + kk + part;
        uint32_t sa = sbase + (uint32_t)(s * STAGE_ELEMS + row * ROWP + part) * 2;
        CP16(sa, ah);                   CP16(sa + 16, ah + 8);
        CP16(sa + TILE_BYTES, al);      CP16(sa + TILE_BYTES + 16, al + 8);
        CP16(sa + 2 * TILE_BYTES, bg);  CP16(sa + 2 * TILE_BYTES + 16, bg + 8);
    };

    load_chunk(0, 0); CP_COMMIT();
    load_chunk(1, 1); CP_COMMIT();

    // ldmatrix lane coords
    const int a_lrow = lane & 15;            // A: 16 rows per x4
    const int a_lcol = (lane >> 4) << 3;     //    2 k-halves
    const int b_nrow = ((lane >> 4) << 3) + (lane & 7);  // B: n within 16
    const int b_kcol = ((lane >> 3) & 1) << 3;           //    k half

    int sc = 0;
    for (int c = 0; c < C; ++c) {
        CP_WAIT1();
        __syncthreads();
        if (c + 2 < C) {
            int s2 = sc + 2; if (s2 >= 3) s2 -= 3;
            load_chunk(c + 2, s2);
        }
        CP_COMMIT();

        const uint32_t aHb = sbase + (uint32_t)(sc * STAGE_ELEMS) * 2;
        const uint32_t aLb = aHb + TILE_BYTES;
        const uint32_t bBb = aHb + 2 * TILE_BYTES;

#pragma unroll
        for (int ks = 0; ks < 2; ++ks) {
            const int kb = ks * 16;
            // B fragments: 8 ni via 4 ldmatrix.x4 (2 ni each)
            uint32_t bf[8][2];
#pragma unroll
            for (int j = 0; j < 4; ++j) {
                uint32_t r[4];
                uint32_t ad = bBb + (uint32_t)((wn * 64 + j * 16 + b_nrow) * ROWP
                                               + kb + b_kcol) * 2;
                ldm_x4(r, ad);
                bf[j * 2 + 0][0] = r[0]; bf[j * 2 + 0][1] = r[1];
                bf[j * 2 + 1][0] = r[2]; bf[j * 2 + 1][1] = r[3];
            }
            // A fragments: 2 mi, hi+lo
            uint32_t ah[2][4], al[2][4];
#pragma unroll
            for (int mi = 0; mi < 2; ++mi) {
                uint32_t off = (uint32_t)((wm * 32 + mi * 16 + a_lrow) * ROWP
                                          + kb + a_lcol) * 2;
                ldm_x4(ah[mi], aHb + off);
                ldm_x4(al[mi], aLb + off);
            }
#pragma unroll
            for (int mi = 0; mi < 2; ++mi)
#pragma unroll
                for (int ni = 0; ni < 8; ++ni) {
                    mma16816(acc[mi][ni], ah[mi], bf[ni][0], bf[ni][1]);
                    mma16816(acc[mi][ni], al[mi], bf[ni][0], bf[ni][1]);
                }
        }
        ++sc; if (sc == 3) sc = 0;
    }

    // ---------------- epilogue ----------------
    const int r_lane = lane >> 2;
    const int c_lane = (lane & 3) * 2;
    const bool is_r = (mode == 0) && (bn < 1024);

#pragma unroll
    for (int mi = 0; mi < 2; ++mi) {
        const int r0 = bm + wm * 32 + mi * 16 + r_lane;
#pragma unroll
        for (int ni = 0; ni < 8; ++ni) {
            const int n_ = bn + wn * 64 + ni * 8 + c_lane;
            const int gn = (mode == 0 && n_ >= 1024) ? n_ - 1024 : n_;
            float bs0, bs1;
            if (mode == 1 || is_r) { bs0 = bi0[gn] + bh0[gn]; bs1 = bi0[gn + 1] + bh0[gn + 1]; }
            else                   { bs0 = bi1[gn] + bh1[gn]; bs1 = bi1[gn + 1] + bh1[gn + 1]; }
#pragma unroll
            for (int h = 0; h < 2; ++h) {
                const int rr = r0 + h * 8;
                const size_t idx = (size_t)rr * HDIM + gn;
                float v0 = acc[mi][ni][h * 2 + 0] + bs0;
                float v1 = acc[mi][ni][h * 2 + 1] + bs1;
                if (mode == 0) {
                    if (is_r) {
                        float2 hv = *(const float2*)(hid + idx);
                        float rv0 = hv.x * sigm(v0);
                        float rv1 = hv.y * sigm(v1);
                        __half h0 = __float2half(rv0);
                        __half h1 = __float2half(rv1);
                        *(__half2*)(g_RHh + idx) = __halves2half2(h0, h1);
                        __half l0 = __float2half(rv0 - __half2float(h0));
                        __half l1 = __float2half(rv1 - __half2float(h1));
                        *(__half2*)(g_RHl + idx) = __halves2half2(l0, l1);
                    } else {
                        *(float2*)(g_zb + idx) = make_float2(sigm(v0), sigm(v1));
                    }
                } else {
                    float2 zv = *(const float2*)(g_zb + idx);
                    float2 hv = *(const float2*)(hid + idx);
                    float t0 = tanhf(v0), t1 = tanhf(v1);
                    float2 o;
                    o.x = zv.x * hv.x + (1.0f - zv.x) * t0;
                    o.y = zv.y * hv.y + (1.0f - zv.y) * t1;
                    *(float2*)(outf + idx) = o;
                }
            }
        }
    }
}

// ---------------- log-softmax over rows of new_hidden ----------------
__global__ __launch_bounds__(256)
void logsoftmax_kernel(const float* __restrict__ nh, float* __restrict__ out)
{
    __shared__ float red[256];
    const int row = blockIdx.x;
    const int tid = threadIdx.x;
    const size_t base = (size_t)row * HDIM + tid * 4;
    const float4 v = *(const float4*)(nh + base);

    float m = fmaxf(fmaxf(v.x, v.y), fmaxf(v.z, v.w));
    red[tid] = m;
    __syncthreads();
#pragma unroll
    for (int s = 128; s >= 1; s >>= 1) {
        if (tid < s) red[tid] = fmaxf(red[tid], red[tid + s]);
        __syncthreads();
    }
    m = red[0];
    __syncthreads();

    float sum = expf(v.x - m) + expf(v.y - m) + expf(v.z - m) + expf(v.w - m);
    red[tid] = sum;
    __syncthreads();
#pragma unroll
    for (int s = 128; s >= 1; s >>= 1) {
        if (tid < s) red[tid] += red[tid + s];
        __syncthreads();
    }
    const float lse = m + logf(red[0]);
    float4 o = make_float4(v.x - lse, v.y - lse, v.z - lse, v.w - lse);
    *(float4*)(out + base) = o;
}

// ---------------- launch ----------------
extern "C" void kernel_launch(void* const* d_in, const int* in_sizes, int n_in,
                              void* d_out, int out_size)
{
    const float* input  = (const float*)d_in[0];
    const float* hidden = (const float*)d_in[1];
    const float* Wir = (const float*)d_in[2];
    const float* bir = (const float*)d_in[3];
    const float* Whr = (const float*)d_in[4];
    const float* bhr = (const float*)d_in[5];
    const float* Wiz = (const float*)d_in[6];
    const float* biz = (const float*)d_in[7];
    const float* Whz = (const float*)d_in[8];
    const float* bhz = (const float*)d_in[9];
    const float* Wih = (const float*)d_in[10];
    const float* bih = (const float*)d_in[11];
    const float* Whh = (const float*)d_in[12];
    const float* bhh = (const float*)d_in[13];

    float* out  = (float*)d_out;
    float* newh = out + (size_t)BDIM * HDIM;

    cudaFuncSetAttribute(gemm_mma, cudaFuncAttributeMaxDynamicSharedMemorySize, SMEM_BYTES);

    const int T_ACT = BDIM * 1024 / 4;
    const int T_W = 1024 * 1024 / 4;
    {
        dim3 ga((T_ACT + 255) / 256, 2);
        convert_act<<<ga, 256>>>(input, hidden, T_ACT);
        dim3 gw((T_W + 255) / 256, 1, 6);
        convert_w<<<gw, 256>>>(Wir, Whr, Wiz, Whz, Wih, Whh, T_W);
    }

    // fused r+z GEMM: N=2048
    dim3 grid1(2048 / 128, BDIM / 128);      // (16, 64)
    gemm_mma<<<grid1, 256, SMEM_BYTES>>>(0, bir, bhr, biz, bhz, hidden, nullptr);
    // candidate GEMM: N=1024, A=[input | r*h]
    dim3 grid2(HDIM / 128, BDIM / 128);      // (8, 64)
    gemm_mma<<<grid2, 256, SMEM_BYTES>>>(1, bih, bhh, nullptr, nullptr, hidden, newh);

    logsoftmax_kernel<<<BDIM, 256>>>(newh, out);
}

// round 6
// speedup vs baseline: 3.2640x; 1.0910x over previous
#include <cuda_runtime.h>
#include <cuda_fp16.h>
#include <cstdint>

#define BDIM 8192
#define HDIM 1024

// ---------------- scratch (__device__ globals; no allocation) ----------------
__device__ __half g_XH[(size_t)BDIM * 2048];   // [input_hi | hidden_hi] fp16
__device__ __half g_XL[(size_t)BDIM * 2048];   // [input_lo | hidden_lo] fp16
__device__ __half g_RHh[(size_t)BDIM * 1024];  // hi(r*hidden)
__device__ __half g_RHl[(size_t)BDIM * 1024];  // lo(r*hidden)
__device__ __half g_Wrz[(size_t)2048 * 2048];  // rows: [Wr|Wz] gates, cols: [Wi|Wh]
__device__ __half g_Wch[(size_t)1024 * 2048];  // rows: Wh gate,     cols: [Wih|Whh]
__device__ float  g_zb[(size_t)BDIM * 1024];   // z gate fp32

// ---------------- helpers ----------------
__device__ __forceinline__ uint32_t smem_u32(const void* p) {
    uint32_t a;
    asm("{ .reg .u64 t; cvta.to.shared.u64 t, %1; cvt.u32.u64 %0, t; }"
        : "=r"(a) : "l"(p));
    return a;
}
#define CP16(sa, ga) \
    asm volatile("cp.async.cg.shared.global [%0], [%1], 16;" :: "r"(sa), "l"(ga) : "memory")
#define CP_COMMIT() asm volatile("cp.async.commit_group;" ::: "memory")
#define CP_WAIT2()  asm volatile("cp.async.wait_group 2;" ::: "memory")

__device__ __forceinline__ void ldm_x4(uint32_t* r, uint32_t addr) {
    asm volatile("ldmatrix.sync.aligned.m8n8.x4.shared.b16 {%0,%1,%2,%3}, [%4];"
                 : "=r"(r[0]), "=r"(r[1]), "=r"(r[2]), "=r"(r[3]) : "r"(addr));
}
__device__ __forceinline__ void mma16816(float* d, const uint32_t* a,
                                         uint32_t b0, uint32_t b1) {
    asm volatile(
        "mma.sync.aligned.m16n8k16.row.col.f32.f16.f16.f32 "
        "{%0,%1,%2,%3}, {%4,%5,%6,%7}, {%8,%9}, {%0,%1,%2,%3};"
        : "+f"(d[0]), "+f"(d[1]), "+f"(d[2]), "+f"(d[3])
        : "r"(a[0]), "r"(a[1]), "r"(a[2]), "r"(a[3]), "r"(b0), "r"(b1));
}
__device__ __forceinline__ float sigm(float x) { return 1.0f / (1.0f + __expf(-x)); }

// smem geometry: 64B rows (32 halves), quad-XOR swizzle -> conflict-free ldmatrix
// quad index q (16B units within row) stored at q ^ ((row>>1)&3)
#define TILE_B 8192                    // 128 rows * 64 B
#define STAGE_B (3 * TILE_B)           // Ah + Al + B = 24576 B
#define NSTAGE 4
#define SMEM_BYTES (NSTAGE * STAGE_B)  // 98304 B

__device__ __forceinline__ uint32_t swq(int row, int q) {
    return (uint32_t)(q ^ ((row >> 1) & 3));
}

// ---------------- converts ----------------
__global__ void convert_act(const float* __restrict__ a, const float* __restrict__ b,
                            int total4)
{
    int i = blockIdx.x * blockDim.x + threadIdx.x;
    if (i >= total4) return;
    const float* src = blockIdx.y ? b : a;
    const int coff = blockIdx.y ? 1024 : 0;
    int e = i * 4;
    int row = e >> 10;
    int col = e & 1023;
    float4 v = *(const float4*)(src + e);
    __half h0 = __float2half(v.x), h1 = __float2half(v.y);
    __half h2 = __float2half(v.z), h3 = __float2half(v.w);
    __half l0 = __float2half(v.x - __half2float(h0));
    __half l1 = __float2half(v.y - __half2float(h1));
    __half l2 = __float2half(v.z - __half2float(h2));
    __half l3 = __float2half(v.w - __half2float(h3));
    size_t d = (size_t)row * 2048 + coff + col;
    *(__half2*)(g_XH + d)     = __halves2half2(h0, h1);
    *(__half2*)(g_XH + d + 2) = __halves2half2(h2, h3);
    *(__half2*)(g_XL + d)     = __halves2half2(l0, l1);
    *(__half2*)(g_XL + d + 2) = __halves2half2(l2, l3);
}

__global__ void convert_w(const float* __restrict__ Wir, const float* __restrict__ Whr,
                          const float* __restrict__ Wiz, const float* __restrict__ Whz,
                          const float* __restrict__ Wih, const float* __restrict__ Whh,
                          int total4)
{
    int i = blockIdx.x * blockDim.x + threadIdx.x;
    if (i >= total4) return;
    const int z = blockIdx.z;
    const float* src = (z == 0) ? Wir : (z == 1) ? Whr : (z == 2) ? Wiz
                     : (z == 3) ? Whz : (z == 4) ? Wih : Whh;
    __half* dst = (z < 4) ? g_Wrz : g_Wch;
    const int roff = (z == 2 || z == 3) ? 1024 : 0;
    const int coff = (z & 1) ? 1024 : 0;
    int e = i * 4;
    int row = e >> 10;
    int col = e & 1023;
    float4 v = *(const float4*)(src + e);
    size_t d = (size_t)(roff + row) * 2048 + coff + col;
    *(__half2*)(dst + d)     = __halves2half2(__float2half(v.x), __float2half(v.y));
    *(__half2*)(dst + d + 2) = __halves2half2(__float2half(v.z), __float2half(v.w));
}

// ---------------- HMMA GEMM, fp16 2-term (A hi/lo, B single) ----------------
// warp grid 4x2: warp tile 32 rows x 64 cols; 4-stage cp.async, wait_group 2
// mode 0: N=2048 rz-GEMM over A=[in|hid]; bn<1024 -> r epilogue, else z
// mode 1: N=1024 candidate GEMM over A=[in|r*h]; newh epilogue -> outf
__global__ __launch_bounds__(256, 2)
void gemm_mma(int mode,
              const float* __restrict__ bi0, const float* __restrict__ bh0,
              const float* __restrict__ bi1, const float* __restrict__ bh1,
              const float* __restrict__ hid, float* __restrict__ outf)
{
    extern __shared__ __half smem[];
    const uint32_t sbase = smem_u32(smem);

    const int tid  = threadIdx.x;
    const int wid  = tid >> 5;
    const int lane = tid & 31;
    const int wm   = wid & 3;      // 4 warp rows (32 rows each)
    const int wn   = wid >> 2;     // 2 warp cols (64 cols each)
    const int bm   = blockIdx.y * 128;
    const int bn   = blockIdx.x * 128;

    const __half* Bw = (mode == 0) ? g_Wrz : g_Wch;

    const int row  = tid >> 1;          // loader row 0..127
    const int q0   = (tid & 1) * 2;     // loader quad base (0 or 2)

    float acc[2][8][4];
#pragma unroll
    for (int i = 0; i < 2; i++)
#pragma unroll
        for (int j = 0; j < 8; j++) {
            acc[i][j][0] = 0.f; acc[i][j][1] = 0.f;
            acc[i][j][2] = 0.f; acc[i][j][3] = 0.f;
        }

    const int C = 64;   // K=2048, chunk=32

    // loader swizzled dest offsets (row fixed per thread)
    const uint32_t ld_base = (uint32_t)row * 64;
    const uint32_t ld_o0 = ld_base + swq(row, q0) * 16;
    const uint32_t ld_o1 = ld_base + swq(row, q0 + 1) * 16;

    auto load_chunk = [&](int c, int s) {
        const int kk = c << 5;
        const __half *Ah, *Al;
        int lda, col;
        if (mode == 1 && kk >= 1024) { Ah = g_RHh; Al = g_RHl; lda = 1024; col = kk - 1024; }
        else                         { Ah = g_XH;  Al = g_XL;  lda = 2048; col = kk; }
        const __half* ah = Ah + (size_t)(bm + row) * lda + col + q0 * 8;
        const __half* al = Al + (size_t)(bm + row) * lda + col + q0 * 8;
        const __half* bg = Bw + (size_t)(bn + row) * 2048 + kk + q0 * 8;
        const uint32_t st = sbase + (uint32_t)s * STAGE_B;
        CP16(st + ld_o0, ah);               CP16(st + ld_o1, ah + 8);
        CP16(st + TILE_B + ld_o0, al);      CP16(st + TILE_B + ld_o1, al + 8);
        CP16(st + 2 * TILE_B + ld_o0, bg);  CP16(st + 2 * TILE_B + ld_o1, bg + 8);
    };

    load_chunk(0, 0); CP_COMMIT();
    load_chunk(1, 1); CP_COMMIT();
    load_chunk(2, 2); CP_COMMIT();

    // ldmatrix lane coords
    const int a_lrow = lane & 15;                        // A: 16 rows per x4
    const int a_q    = lane >> 4;                        //    k-half quad 0/1
    const int b_nrow = ((lane >> 4) << 3) + (lane & 7);  // B: n within 16
    const int b_q    = (lane >> 3) & 1;                  //    k-half quad 0/1

    // precomputed A row offsets (per mi)
    uint32_t a_roff[2], a_rsw[2];
#pragma unroll
    for (int mi = 0; mi < 2; ++mi) {
        int r = wm * 32 + mi * 16 + a_lrow;
        a_roff[mi] = (uint32_t)r * 64;
        a_rsw[mi] = (uint32_t)((r >> 1) & 3);
    }
    uint32_t b_roff[4], b_rsw[4];
#pragma unroll
    for (int j = 0; j < 4; ++j) {
        int r = wn * 64 + j * 16 + b_nrow;
        b_roff[j] = (uint32_t)r * 64;
        b_rsw[j] = (uint32_t)((r >> 1) & 3);
    }

    for (int c = 0; c < C; ++c) {
        CP_WAIT2();
        __syncthreads();
        if (c + 3 < C) load_chunk(c + 3, (c + 3) & 3);
        CP_COMMIT();

        const uint32_t aHb = sbase + (uint32_t)(c & 3) * STAGE_B;
        const uint32_t aLb = aHb + TILE_B;
        const uint32_t bBb = aHb + 2 * TILE_B;

#pragma unroll
        for (int ks = 0; ks < 2; ++ks) {
            const int kq = ks * 2;
            // B fragments: 8 ni via 4 ldmatrix.x4
            uint32_t bf[8][2];
#pragma unroll
            for (int j = 0; j < 4; ++j) {
                uint32_t r[4];
                uint32_t ad = bBb + b_roff[j] + ((uint32_t)(kq + b_q) ^ b_rsw[j]) * 16;
                ldm_x4(r, ad);
                bf[j * 2 + 0][0] = r[0]; bf[j * 2 + 0][1] = r[1];
                bf[j * 2 + 1][0] = r[2]; bf[j * 2 + 1][1] = r[3];
            }
            // A fragments: 2 mi, hi+lo
            uint32_t ah[2][4], al[2][4];
#pragma unroll
            for (int mi = 0; mi < 2; ++mi) {
                uint32_t off = a_roff[mi] + ((uint32_t)(kq + a_q) ^ a_rsw[mi]) * 16;
                ldm_x4(ah[mi], aHb + off);
                ldm_x4(al[mi], aLb + off);
            }
#pragma unroll
            for (int mi = 0; mi < 2; ++mi)
#pragma unroll
                for (int ni = 0; ni < 8; ++ni) {
                    mma16816(acc[mi][ni], ah[mi], bf[ni][0], bf[ni][1]);
                    mma16816(acc[mi][ni], al[mi], bf[ni][0], bf[ni][1]);
                }
        }
    }

    // ---------------- epilogue ----------------
    const int r_lane = lane >> 2;
    const int c_lane = (lane & 3) * 2;
    const bool is_r = (mode == 0) && (bn < 1024);

#pragma unroll
    for (int mi = 0; mi < 2; ++mi) {
        const int r0 = bm + wm * 32 + mi * 16 + r_lane;
#pragma unroll
        for (int ni = 0; ni < 8; ++ni) {
            const int n_ = bn + wn * 64 + ni * 8 + c_lane;
            const int gn = (mode == 0 && n_ >= 1024) ? n_ - 1024 : n_;
            float bs0, bs1;
            if (mode == 1 || is_r) { bs0 = bi0[gn] + bh0[gn]; bs1 = bi0[gn + 1] + bh0[gn + 1]; }
            else                   { bs0 = bi1[gn] + bh1[gn]; bs1 = bi1[gn + 1] + bh1[gn + 1]; }
#pragma unroll
            for (int h = 0; h < 2; ++h) {
                const int rr = r0 + h * 8;
                const size_t idx = (size_t)rr * HDIM + gn;
                float v0 = acc[mi][ni][h * 2 + 0] + bs0;
                float v1 = acc[mi][ni][h * 2 + 1] + bs1;
                if (mode == 0) {
                    if (is_r) {
                        float2 hv = *(const float2*)(hid + idx);
                        float rv0 = hv.x * sigm(v0);
                        float rv1 = hv.y * sigm(v1);
                        __half h0 = __float2half(rv0);
                        __half h1 = __float2half(rv1);
                        *(__half2*)(g_RHh + idx) = __halves2half2(h0, h1);
                        __half l0 = __float2half(rv0 - __half2float(h0));
                        __half l1 = __float2half(rv1 - __half2float(h1));
                        *(__half2*)(g_RHl + idx) = __halves2half2(l0, l1);
                    } else {
                        *(float2*)(g_zb + idx) = make_float2(sigm(v0), sigm(v1));
                    }
                } else {
                    float2 zv = *(const float2*)(g_zb + idx);
                    float2 hv = *(const float2*)(hid + idx);
                    float t0 = tanhf(v0), t1 = tanhf(v1);
                    float2 o;
                    o.x = zv.x * hv.x + (1.0f - zv.x) * t0;
                    o.y = zv.y * hv.y + (1.0f - zv.y) * t1;
                    *(float2*)(outf + idx) = o;
                }
            }
        }
    }
}

// ---------------- log-softmax over rows of new_hidden ----------------
__global__ __launch_bounds__(256)
void logsoftmax_kernel(const float* __restrict__ nh, float* __restrict__ out)
{
    __shared__ float red[256];
    const int row = blockIdx.x;
    const int tid = threadIdx.x;
    const size_t base = (size_t)row * HDIM + tid * 4;
    const float4 v = *(const float4*)(nh + base);

    float m = fmaxf(fmaxf(v.x, v.y), fmaxf(v.z, v.w));
    red[tid] = m;
    __syncthreads();
#pragma unroll
    for (int s = 128; s >= 1; s >>= 1) {
        if (tid < s) red[tid] = fmaxf(red[tid], red[tid + s]);
        __syncthreads();
    }
    m = red[0];
    __syncthreads();

    float sum = expf(v.x - m) + expf(v.y - m) + expf(v.z - m) + expf(v.w - m);
    red[tid] = sum;
    __syncthreads();
#pragma unroll
    for (int s = 128; s >= 1; s >>= 1) {
        if (tid < s) red[tid] += red[tid + s];
        __syncthreads();
    }
    const float lse = m + logf(red[0]);
    float4 o = make_float4(v.x - lse, v.y - lse, v.z - lse, v.w - lse);
    *(float4*)(out + base) = o;
}

// ---------------- launch ----------------
extern "C" void kernel_launch(void* const* d_in, const int* in_sizes, int n_in,
                              void* d_out, int out_size)
{
    const float* input  = (const float*)d_in[0];
    const float* hidden = (const float*)d_in[1];
    const float* Wir = (const float*)d_in[2];
    const float* bir = (const float*)d_in[3];
    const float* Whr = (const float*)d_in[4];
    const float* bhr = (const float*)d_in[5];
    const float* Wiz = (const float*)d_in[6];
    const float* biz = (const float*)d_in[7];
    const float* Whz = (const float*)d_in[8];
    const float* bhz = (const float*)d_in[9];
    const float* Wih = (const float*)d_in[10];
    const float* bih = (const float*)d_in[11];
    const float* Whh = (const float*)d_in[12];
    const float* bhh = (const float*)d_in[13];

    float* out  = (float*)d_out;
    float* newh = out + (size_t)BDIM * HDIM;

    cudaFuncSetAttribute(gemm_mma, cudaFuncAttributeMaxDynamicSharedMemorySize, SMEM_BYTES);

    const int T_ACT = BDIM * 1024 / 4;
    const int T_W = 1024 * 1024 / 4;
    {
        dim3 ga((T_ACT + 255) / 256, 2);
        convert_act<<<ga, 256>>>(input, hidden, T_ACT);
        dim3 gw((T_W + 255) / 256, 1, 6);
        convert_w<<<gw, 256>>>(Wir, Whr, Wiz, Whz, Wih, Whh, T_W);
    }

    // fused r+z GEMM: N=2048
    dim3 grid1(2048 / 128, BDIM / 128);      // (16, 64)
    gemm_mma<<<grid1, 256, SMEM_BYTES>>>(0, bir, bhr, biz, bhz, hidden, nullptr);
    // candidate GEMM: N=1024, A=[input | r*h]
    dim3 grid2(HDIM / 128, BDIM / 128);      // (8, 64)
    gemm_mma<<<grid2, 256, SMEM_BYTES>>>(1, bih, bhh, nullptr, nullptr, hidden, newh);

    logsoftmax_kernel<<<BDIM, 256>>>(newh, out);
}

// round 7
// speedup vs baseline: 3.2746x; 1.0033x over previous
#include <cuda_runtime.h>
#include <cuda_fp16.h>
#include <cstdint>

#define BDIM 8192
#define HDIM 1024

// ---------------- scratch (__device__ globals; no allocation) ----------------
__device__ __half g_XH[(size_t)BDIM * 2048];   // [input_hi | hidden_hi] fp16
__device__ __half g_XL[(size_t)BDIM * 2048];   // [input_lo | hidden_lo] fp16
__device__ __half g_RHh[(size_t)BDIM * 1024];  // hi(r*hidden)
__device__ __half g_RHl[(size_t)BDIM * 1024];  // lo(r*hidden)
__device__ __half g_Wrz[(size_t)2048 * 2048];  // rows: [Wr|Wz] gates, cols: [Wi|Wh]
__device__ __half g_Wch[(size_t)1024 * 2048];  // rows: Wh gate,     cols: [Wih|Whh]
__device__ float  g_zb[(size_t)BDIM * 1024];   // z gate fp32

// ---------------- helpers ----------------
__device__ __forceinline__ uint32_t smem_u32(const void* p) {
    uint32_t a;
    asm("{ .reg .u64 t; cvta.to.shared.u64 t, %1; cvt.u32.u64 %0, t; }"
        : "=r"(a) : "l"(p));
    return a;
}
#define CP16(sa, ga) \
    asm volatile("cp.async.cg.shared.global [%0], [%1], 16;" :: "r"(sa), "l"(ga) : "memory")
#define CP_COMMIT() asm volatile("cp.async.commit_group;" ::: "memory")
#define CP_WAIT1()  asm volatile("cp.async.wait_group 1;" ::: "memory")

__device__ __forceinline__ void ldm_x4(uint32_t* r, uint32_t addr) {
    asm volatile("ldmatrix.sync.aligned.m8n8.x4.shared.b16 {%0,%1,%2,%3}, [%4];"
                 : "=r"(r[0]), "=r"(r[1]), "=r"(r[2]), "=r"(r[3]) : "r"(addr));
}
__device__ __forceinline__ void mma16816(float* d, const uint32_t* a,
                                         uint32_t b0, uint32_t b1) {
    asm volatile(
        "mma.sync.aligned.m16n8k16.row.col.f32.f16.f16.f32 "
        "{%0,%1,%2,%3}, {%4,%5,%6,%7}, {%8,%9}, {%0,%1,%2,%3};"
        : "+f"(d[0]), "+f"(d[1]), "+f"(d[2]), "+f"(d[3])
        : "r"(a[0]), "r"(a[1]), "r"(a[2]), "r"(a[3]), "r"(b0), "r"(b1));
}
__device__ __forceinline__ float sigm(float x) { return 1.0f / (1.0f + __expf(-x)); }

// smem: 64B rows (32 halves), quad-XOR swizzle (q ^= (row>>1)&3), conflict-free
// stage = Ah(128x32) + Al(128x32) + B(64x32) = 8192+8192+4096 = 20480 B
#define A_TILE_B 8192
#define B_TILE_B 4096
#define OFF_AL A_TILE_B
#define OFF_B  (2 * A_TILE_B)
#define STAGE_B (2 * A_TILE_B + B_TILE_B)    // 20480
#define NSTAGE 3
#define SMEM_BYTES (NSTAGE * STAGE_B)        // 61440

__device__ __forceinline__ uint32_t swq(int row, int q) {
    return (uint32_t)(q ^ ((row >> 1) & 3));
}

// ---------------- converts ----------------
__global__ void convert_act(const float* __restrict__ a, const float* __restrict__ b,
                            int total4)
{
    int i = blockIdx.x * blockDim.x + threadIdx.x;
    if (i >= total4) return;
    const float* src = blockIdx.y ? b : a;
    const int coff = blockIdx.y ? 1024 : 0;
    int e = i * 4;
    int row = e >> 10;
    int col = e & 1023;
    float4 v = *(const float4*)(src + e);
    __half h0 = __float2half(v.x), h1 = __float2half(v.y);
    __half h2 = __float2half(v.z), h3 = __float2half(v.w);
    __half l0 = __float2half(v.x - __half2float(h0));
    __half l1 = __float2half(v.y - __half2float(h1));
    __half l2 = __float2half(v.z - __half2float(h2));
    __half l3 = __float2half(v.w - __half2float(h3));
    size_t d = (size_t)row * 2048 + coff + col;
    *(__half2*)(g_XH + d)     = __halves2half2(h0, h1);
    *(__half2*)(g_XH + d + 2) = __halves2half2(h2, h3);
    *(__half2*)(g_XL + d)     = __halves2half2(l0, l1);
    *(__half2*)(g_XL + d + 2) = __halves2half2(l2, l3);
}

__global__ void convert_w(const float* __restrict__ Wir, const float* __restrict__ Whr,
                          const float* __restrict__ Wiz, const float* __restrict__ Whz,
                          const float* __restrict__ Wih, const float* __restrict__ Whh,
                          int total4)
{
    int i = blockIdx.x * blockDim.x + threadIdx.x;
    if (i >= total4) return;
    const int z = blockIdx.z;
    const float* src = (z == 0) ? Wir : (z == 1) ? Whr : (z == 2) ? Wiz
                     : (z == 3) ? Whz : (z == 4) ? Wih : Whh;
    __half* dst = (z < 4) ? g_Wrz : g_Wch;
    const int roff = (z == 2 || z == 3) ? 1024 : 0;
    const int coff = (z & 1) ? 1024 : 0;
    int e = i * 4;
    int row = e >> 10;
    int col = e & 1023;
    float4 v = *(const float4*)(src + e);
    size_t d = (size_t)(roff + row) * 2048 + coff + col;
    *(__half2*)(dst + d)     = __halves2half2(__float2half(v.x), __float2half(v.y));
    *(__half2*)(dst + d + 2) = __halves2half2(__float2half(v.z), __float2half(v.w));
}

// ---------------- HMMA GEMM, fp16 2-term (A hi/lo, B single) ----------------
// CTA tile 128(M) x 64(N); warp grid 4x2, warp tile 32x32; 3 CTAs/SM
// mode 0: N=2048 rz-GEMM over A=[in|hid]; bn<1024 -> r epilogue, else z
// mode 1: N=1024 candidate GEMM over A=[in|r*h]; newh epilogue -> outf
__global__ __launch_bounds__(256, 3)
void gemm_mma(int mode,
              const float* __restrict__ bi0, const float* __restrict__ bh0,
              const float* __restrict__ bi1, const float* __restrict__ bh1,
              const float* __restrict__ hid, float* __restrict__ outf)
{
    extern __shared__ __half smem[];
    const uint32_t sbase = smem_u32(smem);

    const int tid  = threadIdx.x;
    const int wid  = tid >> 5;
    const int lane = tid & 31;
    const int wm   = wid & 3;      // 4 warp rows (32 rows each)
    const int wn   = wid >> 2;     // 2 warp cols (32 cols each)
    const int bm   = blockIdx.y * 128;
    const int bn   = blockIdx.x * 64;

    const __half* Bw = (mode == 0) ? g_Wrz : g_Wch;

    // loader coords: A rows 0..127 (2 quads/thread), B rows 0..63 (1 quad/thread)
    const int arow = tid >> 1;
    const int aq0  = (tid & 1) * 2;
    const int brow = tid >> 2;
    const int bq   = tid & 3;

    float acc[2][4][4];
#pragma unroll
    for (int i = 0; i < 2; i++)
#pragma unroll
        for (int j = 0; j < 4; j++) {
            acc[i][j][0] = 0.f; acc[i][j][1] = 0.f;
            acc[i][j][2] = 0.f; acc[i][j][3] = 0.f;
        }

    const int C = 64;   // K=2048, chunk=32

    const uint32_t a_o0 = (uint32_t)arow * 64 + swq(arow, aq0) * 16;
    const uint32_t a_o1 = (uint32_t)arow * 64 + swq(arow, aq0 + 1) * 16;
    const uint32_t b_o  = (uint32_t)brow * 64 + swq(brow, bq) * 16;

    auto load_chunk = [&](int c, int s) {
        const int kk = c << 5;
        const __half *Ah, *Al;
        int lda, col;
        if (mode == 1 && kk >= 1024) { Ah = g_RHh; Al = g_RHl; lda = 1024; col = kk - 1024; }
        else                         { Ah = g_XH;  Al = g_XL;  lda = 2048; col = kk; }
        const __half* ah = Ah + (size_t)(bm + arow) * lda + col + aq0 * 8;
        const __half* al = Al + (size_t)(bm + arow) * lda + col + aq0 * 8;
        const __half* bg = Bw + (size_t)(bn + brow) * 2048 + kk + bq * 8;
        const uint32_t st = sbase + (uint32_t)s * STAGE_B;
        CP16(st + a_o0, ah);            CP16(st + a_o1, ah + 8);
        CP16(st + OFF_AL + a_o0, al);   CP16(st + OFF_AL + a_o1, al + 8);
        CP16(st + OFF_B + b_o, bg);
    };

    load_chunk(0, 0); CP_COMMIT();
    load_chunk(1, 1); CP_COMMIT();

    // ldmatrix lane coords
    const int a_lrow = lane & 15;                        // A: 16 rows per x4
    const int a_q    = lane >> 4;                        //    k-half quad
    const int b_nrow = ((lane >> 4) << 3) + (lane & 7);  // B: n within 16
    const int b_q    = (lane >> 3) & 1;                  //    k-half quad

    uint32_t a_roff[2], a_rsw[2];
#pragma unroll
    for (int mi = 0; mi < 2; ++mi) {
        int r = wm * 32 + mi * 16 + a_lrow;
        a_roff[mi] = (uint32_t)r * 64;
        a_rsw[mi] = (uint32_t)((r >> 1) & 3);
    }
    uint32_t b_roff[2], b_rsw[2];
#pragma unroll
    for (int j = 0; j < 2; ++j) {
        int r = wn * 32 + j * 16 + b_nrow;
        b_roff[j] = (uint32_t)r * 64;
        b_rsw[j] = (uint32_t)((r >> 1) & 3);
    }

    int sc = 0;
    for (int c = 0; c < C; ++c) {
        CP_WAIT1();
        __syncthreads();
        if (c + 2 < C) {
            int s2 = sc + 2; if (s2 >= 3) s2 -= 3;
            load_chunk(c + 2, s2);
        }
        CP_COMMIT();

        const uint32_t aHb = sbase + (uint32_t)sc * STAGE_B;
        const uint32_t aLb = aHb + OFF_AL;
        const uint32_t bBb = aHb + OFF_B;

#pragma unroll
        for (int ks = 0; ks < 2; ++ks) {
            const int kq = ks * 2;
            uint32_t bf[4][2];
#pragma unroll
            for (int j = 0; j < 2; ++j) {
                uint32_t r[4];
                uint32_t ad = bBb + b_roff[j] + ((uint32_t)(kq + b_q) ^ b_rsw[j]) * 16;
                ldm_x4(r, ad);
                bf[j * 2 + 0][0] = r[0]; bf[j * 2 + 0][1] = r[1];
                bf[j * 2 + 1][0] = r[2]; bf[j * 2 + 1][1] = r[3];
            }
            uint32_t ah[2][4], al[2][4];
#pragma unroll
            for (int mi = 0; mi < 2; ++mi) {
                uint32_t off = a_roff[mi] + ((uint32_t)(kq + a_q) ^ a_rsw[mi]) * 16;
                ldm_x4(ah[mi], aHb + off);
                ldm_x4(al[mi], aLb + off);
            }
#pragma unroll
            for (int mi = 0; mi < 2; ++mi)
#pragma unroll
                for (int ni = 0; ni < 4; ++ni) {
                    mma16816(acc[mi][ni], ah[mi], bf[ni][0], bf[ni][1]);
                    mma16816(acc[mi][ni], al[mi], bf[ni][0], bf[ni][1]);
                }
        }
        ++sc; if (sc == 3) sc = 0;
    }

    // ---------------- epilogue ----------------
    const int r_lane = lane >> 2;
    const int c_lane = (lane & 3) * 2;
    const bool is_r = (mode == 0) && (bn < 1024);

#pragma unroll
    for (int mi = 0; mi < 2; ++mi) {
        const int r0 = bm + wm * 32 + mi * 16 + r_lane;
#pragma unroll
        for (int ni = 0; ni < 4; ++ni) {
            const int n_ = bn + wn * 32 + ni * 8 + c_lane;
            const int gn = (mode == 0 && n_ >= 1024) ? n_ - 1024 : n_;
            float bs0, bs1;
            if (mode == 1 || is_r) { bs0 = bi0[gn] + bh0[gn]; bs1 = bi0[gn + 1] + bh0[gn + 1]; }
            else                   { bs0 = bi1[gn] + bh1[gn]; bs1 = bi1[gn + 1] + bh1[gn + 1]; }
#pragma unroll
            for (int h = 0; h < 2; ++h) {
                const int rr = r0 + h * 8;
                const size_t idx = (size_t)rr * HDIM + gn;
                float v0 = acc[mi][ni][h * 2 + 0] + bs0;
                float v1 = acc[mi][ni][h * 2 + 1] + bs1;
                if (mode == 0) {
                    if (is_r) {
                        float2 hv = *(const float2*)(hid + idx);
                        float rv0 = hv.x * sigm(v0);
                        float rv1 = hv.y * sigm(v1);
                        __half h0 = __float2half(rv0);
                        __half h1 = __float2half(rv1);
                        *(__half2*)(g_RHh + idx) = __halves2half2(h0, h1);
                        __half l0 = __float2half(rv0 - __half2float(h0));
                        __half l1 = __float2half(rv1 - __half2float(h1));
                        *(__half2*)(g_RHl + idx) = __halves2half2(l0, l1);
                    } else {
                        *(float2*)(g_zb + idx) = make_float2(sigm(v0), sigm(v1));
                    }
                } else {
                    float2 zv = *(const float2*)(g_zb + idx);
                    float2 hv = *(const float2*)(hid + idx);
                    float t0 = tanhf(v0), t1 = tanhf(v1);
                    float2 o;
                    o.x = zv.x * hv.x + (1.0f - zv.x) * t0;
                    o.y = zv.y * hv.y + (1.0f - zv.y) * t1;
                    *(float2*)(outf + idx) = o;
                }
            }
        }
    }
}

// ---------------- log-softmax over rows of new_hidden ----------------
__global__ __launch_bounds__(256)
void logsoftmax_kernel(const float* __restrict__ nh, float* __restrict__ out)
{
    __shared__ float red[256];
    const int row = blockIdx.x;
    const int tid = threadIdx.x;
    const size_t base = (size_t)row * HDIM + tid * 4;
    const float4 v = *(const float4*)(nh + base);

    float m = fmaxf(fmaxf(v.x, v.y), fmaxf(v.z, v.w));
    red[tid] = m;
    __syncthreads();
#pragma unroll
    for (int s = 128; s >= 1; s >>= 1) {
        if (tid < s) red[tid] = fmaxf(red[tid], red[tid + s]);
        __syncthreads();
    }
    m = red[0];
    __syncthreads();

    float sum = expf(v.x - m) + expf(v.y - m) + expf(v.z - m) + expf(v.w - m);
    red[tid] = sum;
    __syncthreads();
#pragma unroll
    for (int s = 128; s >= 1; s >>= 1) {
        if (tid < s) red[tid] += red[tid + s];
        __syncthreads();
    }
    const float lse = m + logf(red[0]);
    float4 o = make_float4(v.x - lse, v.y - lse, v.z - lse, v.w - lse);
    *(float4*)(out + base) = o;
}

// ---------------- launch ----------------
extern "C" void kernel_launch(void* const* d_in, const int* in_sizes, int n_in,
                              void* d_out, int out_size)
{
    const float* input  = (const float*)d_in[0];
    const float* hidden = (const float*)d_in[1];
    const float* Wir = (const float*)d_in[2];
    const float* bir = (const float*)d_in[3];
    const float* Whr = (const float*)d_in[4];
    const float* bhr = (const float*)d_in[5];
    const float* Wiz = (const float*)d_in[6];
    const float* biz = (const float*)d_in[7];
    const float* Whz = (const float*)d_in[8];
    const float* bhz = (const float*)d_in[9];
    const float* Wih = (const float*)d_in[10];
    const float* bih = (const float*)d_in[11];
    const float* Whh = (const float*)d_in[12];
    const float* bhh = (const float*)d_in[13];

    float* out  = (float*)d_out;
    float* newh = out + (size_t)BDIM * HDIM;

    cudaFuncSetAttribute(gemm_mma, cudaFuncAttributeMaxDynamicSharedMemorySize, SMEM_BYTES);

    const int T_ACT = BDIM * 1024 / 4;
    const int T_W = 1024 * 1024 / 4;
    {
        dim3 ga((T_ACT + 255) / 256, 2);
        convert_act<<<ga, 256>>>(input, hidden, T_ACT);
        dim3 gw((T_W + 255) / 256, 1, 6);
        convert_w<<<gw, 256>>>(Wir, Whr, Wiz, Whz, Wih, Whh, T_W);
    }

    // fused r+z GEMM: N=2048
    dim3 grid1(2048 / 64, BDIM / 128);       // (32, 64)
    gemm_mma<<<grid1, 256, SMEM_BYTES>>>(0, bir, bhr, biz, bhz, hidden, nullptr);
    // candidate GEMM: N=1024, A=[input | r*h]
    dim3 grid2(HDIM / 64, BDIM / 128);       // (16, 64)
    gemm_mma<<<grid2, 256, SMEM_BYTES>>>(1, bih, bhh, nullptr, nullptr, hidden, newh);

    logsoftmax_kernel<<<BDIM, 256>>>(newh, out);
}

// round 8
// speedup vs baseline: 3.4509x; 1.0538x over previous
#include <cuda_runtime.h>
#include <cuda_fp16.h>
#include <cstdint>

#define BDIM 8192
#define HDIM 1024

// ---------------- scratch (__device__ globals; no allocation) ----------------
__device__ __half g_XH[(size_t)BDIM * 2048];   // [input | hidden] fp16
__device__ __half g_RH[(size_t)BDIM * 1024];   // r * hidden fp16
__device__ __half g_Wrz[(size_t)2048 * 2048];  // rows: [Wr|Wz] gates, cols: [Wi|Wh]
__device__ __half g_Wch[(size_t)1024 * 2048];  // rows: Wh gate,     cols: [Wih|Whh]
__device__ float  g_zb[(size_t)BDIM * 1024];   // z gate fp32

// ---------------- helpers ----------------
__device__ __forceinline__ uint32_t smem_u32(const void* p) {
    uint32_t a;
    asm("{ .reg .u64 t; cvta.to.shared.u64 t, %1; cvt.u32.u64 %0, t; }"
        : "=r"(a) : "l"(p));
    return a;
}
#define CP16(sa, ga) \
    asm volatile("cp.async.cg.shared.global [%0], [%1], 16;" :: "r"(sa), "l"(ga) : "memory")
#define CP_COMMIT() asm volatile("cp.async.commit_group;" ::: "memory")
#define CP_WAIT2()  asm volatile("cp.async.wait_group 2;" ::: "memory")

__device__ __forceinline__ void ldm_x4(uint32_t* r, uint32_t addr) {
    asm volatile("ldmatrix.sync.aligned.m8n8.x4.shared.b16 {%0,%1,%2,%3}, [%4];"
                 : "=r"(r[0]), "=r"(r[1]), "=r"(r[2]), "=r"(r[3]) : "r"(addr));
}
__device__ __forceinline__ void mma16816(float* d, const uint32_t* a,
                                         uint32_t b0, uint32_t b1) {
    asm volatile(
        "mma.sync.aligned.m16n8k16.row.col.f32.f16.f16.f32 "
        "{%0,%1,%2,%3}, {%4,%5,%6,%7}, {%8,%9}, {%0,%1,%2,%3};"
        : "+f"(d[0]), "+f"(d[1]), "+f"(d[2]), "+f"(d[3])
        : "r"(a[0]), "r"(a[1]), "r"(a[2]), "r"(a[3]), "r"(b0), "r"(b1));
}
__device__ __forceinline__ float sigm(float x) { return 1.0f / (1.0f + __expf(-x)); }

// smem: 64B rows (32 halves), quad-XOR swizzle (q ^= (row>>1)&3), conflict-free
// stage = A(128x32) + B(64x32) = 8192 + 4096 = 12288 B
#define A_TILE_B 8192
#define B_TILE_B 4096
#define OFF_B  A_TILE_B
#define STAGE_B (A_TILE_B + B_TILE_B)        // 12288
#define NSTAGE 4
#define SMEM_BYTES (NSTAGE * STAGE_B)        // 49152

__device__ __forceinline__ uint32_t swq(int row, int q) {
    return (uint32_t)(q ^ ((row >> 1) & 3));
}

// ---------------- converts ----------------
__global__ void convert_act(const float* __restrict__ a, const float* __restrict__ b,
                            int total4)
{
    int i = blockIdx.x * blockDim.x + threadIdx.x;
    if (i >= total4) return;
    const float* src = blockIdx.y ? b : a;
    const int coff = blockIdx.y ? 1024 : 0;
    int e = i * 4;
    int row = e >> 10;
    int col = e & 1023;
    float4 v = *(const float4*)(src + e);
    size_t d = (size_t)row * 2048 + coff + col;
    *(__half2*)(g_XH + d)     = __halves2half2(__float2half(v.x), __float2half(v.y));
    *(__half2*)(g_XH + d + 2) = __halves2half2(__float2half(v.z), __float2half(v.w));
}

__global__ void convert_w(const float* __restrict__ Wir, const float* __restrict__ Whr,
                          const float* __restrict__ Wiz, const float* __restrict__ Whz,
                          const float* __restrict__ Wih, const float* __restrict__ Whh,
                          int total4)
{
    int i = blockIdx.x * blockDim.x + threadIdx.x;
    if (i >= total4) return;
    const int z = blockIdx.z;
    const float* src = (z == 0) ? Wir : (z == 1) ? Whr : (z == 2) ? Wiz
                     : (z == 3) ? Whz : (z == 4) ? Wih : Whh;
    __half* dst = (z < 4) ? g_Wrz : g_Wch;
    const int roff = (z == 2 || z == 3) ? 1024 : 0;
    const int coff = (z & 1) ? 1024 : 0;
    int e = i * 4;
    int row = e >> 10;
    int col = e & 1023;
    float4 v = *(const float4*)(src + e);
    size_t d = (size_t)(roff + row) * 2048 + coff + col;
    *(__half2*)(dst + d)     = __halves2half2(__float2half(v.x), __float2half(v.y));
    *(__half2*)(dst + d + 2) = __halves2half2(__float2half(v.z), __float2half(v.w));
}

// ---------------- HMMA GEMM, single fp16 ----------------
// CTA tile 128(M) x 64(N); warp grid 4x2, warp tile 32x32; 4 CTAs/SM
// mode 0: N=2048 rz-GEMM over A=[in|hid]; bn<1024 -> r epilogue, else z
// mode 1: N=1024 candidate GEMM over A=[in|r*h]; newh epilogue -> outf
__global__ __launch_bounds__(256, 4)
void gemm_mma(int mode,
              const float* __restrict__ bi0, const float* __restrict__ bh0,
              const float* __restrict__ bi1, const float* __restrict__ bh1,
              const float* __restrict__ hid, float* __restrict__ outf)
{
    extern __shared__ __half smem[];
    const uint32_t sbase = smem_u32(smem);

    const int tid  = threadIdx.x;
    const int wid  = tid >> 5;
    const int lane = tid & 31;
    const int wm   = wid & 3;      // 4 warp rows (32 rows each)
    const int wn   = wid >> 2;     // 2 warp cols (32 cols each)
    const int bm   = blockIdx.y * 128;
    const int bn   = blockIdx.x * 64;

    const __half* Bw = (mode == 0) ? g_Wrz : g_Wch;

    // loader coords: A rows 0..127 (2 quads/thread), B rows 0..63 (1 quad/thread)
    const int arow = tid >> 1;
    const int aq0  = (tid & 1) * 2;
    const int brow = tid >> 2;
    const int bq   = tid & 3;

    float acc[2][4][4];
#pragma unroll
    for (int i = 0; i < 2; i++)
#pragma unroll
        for (int j = 0; j < 4; j++) {
            acc[i][j][0] = 0.f; acc[i][j][1] = 0.f;
            acc[i][j][2] = 0.f; acc[i][j][3] = 0.f;
        }

    const int C = 64;   // K=2048, chunk=32

    const uint32_t a_o0 = (uint32_t)arow * 64 + swq(arow, aq0) * 16;
    const uint32_t a_o1 = (uint32_t)arow * 64 + swq(arow, aq0 + 1) * 16;
    const uint32_t b_o  = (uint32_t)brow * 64 + swq(brow, bq) * 16;

    auto load_chunk = [&](int c, int s) {
        const int kk = c << 5;
        const __half* Ah;
        int lda, col;
        if (mode == 1 && kk >= 1024) { Ah = g_RH; lda = 1024; col = kk - 1024; }
        else                         { Ah = g_XH; lda = 2048; col = kk; }
        const __half* ah = Ah + (size_t)(bm + arow) * lda + col + aq0 * 8;
        const __half* bg = Bw + (size_t)(bn + brow) * 2048 + kk + bq * 8;
        const uint32_t st = sbase + (uint32_t)s * STAGE_B;
        CP16(st + a_o0, ah);          CP16(st + a_o1, ah + 8);
        CP16(st + OFF_B + b_o, bg);
    };

    load_chunk(0, 0); CP_COMMIT();
    load_chunk(1, 1); CP_COMMIT();
    load_chunk(2, 2); CP_COMMIT();

    // ldmatrix lane coords
    const int a_lrow = lane & 15;                        // A: 16 rows per x4
    const int a_q    = lane >> 4;                        //    k-half quad
    const int b_nrow = ((lane >> 4) << 3) + (lane & 7);  // B: n within 16
    const int b_q    = (lane >> 3) & 1;                  //    k-half quad

    uint32_t a_roff[2], a_rsw[2];
#pragma unroll
    for (int mi = 0; mi < 2; ++mi) {
        int r = wm * 32 + mi * 16 + a_lrow;
        a_roff[mi] = (uint32_t)r * 64;
        a_rsw[mi] = (uint32_t)((r >> 1) & 3);
    }
    uint32_t b_roff[2], b_rsw[2];
#pragma unroll
    for (int j = 0; j < 2; ++j) {
        int r = wn * 32 + j * 16 + b_nrow;
        b_roff[j] = (uint32_t)r * 64;
        b_rsw[j] = (uint32_t)((r >> 1) & 3);
    }

    for (int c = 0; c < C; ++c) {
        CP_WAIT2();
        __syncthreads();
        if (c + 3 < C) load_chunk(c + 3, (c + 3) & 3);
        CP_COMMIT();

        const uint32_t aHb = sbase + (uint32_t)(c & 3) * STAGE_B;
        const uint32_t bBb = aHb + OFF_B;

#pragma unroll
        for (int ks = 0; ks < 2; ++ks) {
            const int kq = ks * 2;
            uint32_t bf[4][2];
#pragma unroll
            for (int j = 0; j < 2; ++j) {
                uint32_t r[4];
                uint32_t ad = bBb + b_roff[j] + ((uint32_t)(kq + b_q) ^ b_rsw[j]) * 16;
                ldm_x4(r, ad);
                bf[j * 2 + 0][0] = r[0]; bf[j * 2 + 0][1] = r[1];
                bf[j * 2 + 1][0] = r[2]; bf[j * 2 + 1][1] = r[3];
            }
            uint32_t ah[2][4];
#pragma unroll
            for (int mi = 0; mi < 2; ++mi) {
                uint32_t off = a_roff[mi] + ((uint32_t)(kq + a_q) ^ a_rsw[mi]) * 16;
                ldm_x4(ah[mi], aHb + off);
            }
#pragma unroll
            for (int mi = 0; mi < 2; ++mi)
#pragma unroll
                for (int ni = 0; ni < 4; ++ni)
                    mma16816(acc[mi][ni], ah[mi], bf[ni][0], bf[ni][1]);
        }
    }

    // ---------------- epilogue ----------------
    const int r_lane = lane >> 2;
    const int c_lane = (lane & 3) * 2;
    const bool is_r = (mode == 0) && (bn < 1024);

#pragma unroll
    for (int mi = 0; mi < 2; ++mi) {
        const int r0 = bm + wm * 32 + mi * 16 + r_lane;
#pragma unroll
        for (int ni = 0; ni < 4; ++ni) {
            const int n_ = bn + wn * 32 + ni * 8 + c_lane;
            const int gn = (mode == 0 && n_ >= 1024) ? n_ - 1024 : n_;
            float bs0, bs1;
            if (mode == 1 || is_r) { bs0 = bi0[gn] + bh0[gn]; bs1 = bi0[gn + 1] + bh0[gn + 1]; }
            else                   { bs0 = bi1[gn] + bh1[gn]; bs1 = bi1[gn + 1] + bh1[gn + 1]; }
#pragma unroll
            for (int h = 0; h < 2; ++h) {
                const int rr = r0 + h * 8;
                const size_t idx = (size_t)rr * HDIM + gn;
                float v0 = acc[mi][ni][h * 2 + 0] + bs0;
                float v1 = acc[mi][ni][h * 2 + 1] + bs1;
                if (mode == 0) {
                    if (is_r) {
                        float2 hv = *(const float2*)(hid + idx);
                        float rv0 = hv.x * sigm(v0);
                        float rv1 = hv.y * sigm(v1);
                        *(__half2*)(g_RH + idx) =
                            __halves2half2(__float2half(rv0), __float2half(rv1));
                    } else {
                        *(float2*)(g_zb + idx) = make_float2(sigm(v0), sigm(v1));
                    }
                } else {
                    float2 zv = *(const float2*)(g_zb + idx);
                    float2 hv = *(const float2*)(hid + idx);
                    float t0 = tanhf(v0), t1 = tanhf(v1);
                    float2 o;
                    o.x = zv.x * hv.x + (1.0f - zv.x) * t0;
                    o.y = zv.y * hv.y + (1.0f - zv.y) * t1;
                    *(float2*)(outf + idx) = o;
                }
            }
        }
    }
}

// ---------------- log-softmax over rows of new_hidden ----------------
__global__ __launch_bounds__(256)
void logsoftmax_kernel(const float* __restrict__ nh, float* __restrict__ out)
{
    __shared__ float red[256];
    const int row = blockIdx.x;
    const int tid = threadIdx.x;
    const size_t base = (size_t)row * HDIM + tid * 4;
    const float4 v = *(const float4*)(nh + base);

    float m = fmaxf(fmaxf(v.x, v.y), fmaxf(v.z, v.w));
    red[tid] = m;
    __syncthreads();
#pragma unroll
    for (int s = 128; s >= 1; s >>= 1) {
        if (tid < s) red[tid] = fmaxf(red[tid], red[tid + s]);
        __syncthreads();
    }
    m = red[0];
    __syncthreads();

    float sum = expf(v.x - m) + expf(v.y - m) + expf(v.z - m) + expf(v.w - m);
    red[tid] = sum;
    __syncthreads();
#pragma unroll
    for (int s = 128; s >= 1; s >>= 1) {
        if (tid < s) red[tid] += red[tid + s];
        __syncthreads();
    }
    const float lse = m + logf(red[0]);
    float4 o = make_float4(v.x - lse, v.y - lse, v.z - lse, v.w - lse);
    *(float4*)(out + base) = o;
}

// ---------------- launch ----------------
extern "C" void kernel_launch(void* const* d_in, const int* in_sizes, int n_in,
                              void* d_out, int out_size)
{
    const float* input  = (const float*)d_in[0];
    const float* hidden = (const float*)d_in[1];
    const float* Wir = (const float*)d_in[2];
    const float* bir = (const float*)d_in[3];
    const float* Whr = (const float*)d_in[4];
    const float* bhr = (const float*)d_in[5];
    const float* Wiz = (const float*)d_in[6];
    const float* biz = (const float*)d_in[7];
    const float* Whz = (const float*)d_in[8];
    const float* bhz = (const float*)d_in[9];
    const float* Wih = (const float*)d_in[10];
    const float* bih = (const float*)d_in[11];
    const float* Whh = (const float*)d_in[12];
    const float* bhh = (const float*)d_in[13];

    float* out  = (float*)d_out;
    float* newh = out + (size_t)BDIM * HDIM;

    cudaFuncSetAttribute(gemm_mma, cudaFuncAttributeMaxDynamicSharedMemorySize, SMEM_BYTES);

    const int T_ACT = BDIM * 1024 / 4;
    const int T_W = 1024 * 1024 / 4;
    {
        dim3 ga((T_ACT + 255) / 256, 2);
        convert_act<<<ga, 256>>>(input, hidden, T_ACT);
        dim3 gw((T_W + 255) / 256, 1, 6);
        convert_w<<<gw, 256>>>(Wir, Whr, Wiz, Whz, Wih, Whh, T_W);
    }

    // fused r+z GEMM: N=2048
    dim3 grid1(2048 / 64, BDIM / 128);       // (32, 64)
    gemm_mma<<<grid1, 256, SMEM_BYTES>>>(0, bir, bhr, biz, bhz, hidden, nullptr);
    // candidate GEMM: N=1024, A=[input | r*h]
    dim3 grid2(HDIM / 64, BDIM / 128);       // (16, 64)
    gemm_mma<<<grid2, 256, SMEM_BYTES>>>(1, bih, bhh, nullptr, nullptr, hidden, newh);

    logsoftmax_kernel<<<BDIM, 256>>>(newh, out);
}